// round 13
// baseline (speedup 1.0000x reference)
#include <cuda_runtime.h>
#include <cuda_fp16.h>
#include <math.h>
#include <stdint.h>

// ---------------- problem constants ----------------
#define BB   4
#define SS   1024
#define HH   1024
#define NHH  16
#define HDD  64
#define FFF  4096
#define ADD  256
#define MM   (BB*SS)          // 4096 rows
#define EPSF 1e-5f
#define QKVN 3072
#define FAK  (FFF+ADD)        // 4352

// ---------------- scratch ----------------
__device__ __half g_qkv [(size_t)MM*QKVN];
__device__ __half g_ctx [MM*HH];
__device__ float  g_att [MM*HH];
__device__ float  g_h   [MM*HH];
__device__ __half g_hr  [MM*HH];
__device__ __half g_ff1 [(size_t)MM*FAK];
__device__ float  g_ff2 [MM*HH];
__device__ float  g_gate[BB*NHH*SS];
__device__ float  g_pb  [NHH*2048];
// fp16 operand copies
__device__ __half g_xr  [MM*HH];
__device__ __half g_wqkv[QKVN*HH];
__device__ __half g_wo  [HH*HH];
__device__ __half g_w1c [(size_t)FAK*HH];
__device__ __half g_w2c [(size_t)HH*FAK];
__device__ float  g_bqkv[QKVN];
__device__ float  g_b2c [HH];
__device__ float  g_b1c [FAK];
__device__ float  g_wgab[130];

// ---------------- helpers ----------------
__device__ __forceinline__ uint32_t smem_u32(const void* p) {
    uint32_t a;
    asm("{ .reg .u64 t; cvta.to.shared.u64 t, %1; cvt.u32.u64 %0, t; }" : "=r"(a) : "l"(p));
    return a;
}
__device__ __forceinline__ void cp16(uint32_t s, const void* g) {
    asm volatile("cp.async.cg.shared.global [%0], [%1], 16;" :: "r"(s), "l"(g));
}
#define CP_COMMIT() asm volatile("cp.async.commit_group;")
#define CP_WAIT(N)  asm volatile("cp.async.wait_group %0;" :: "n"(N))

__device__ __forceinline__ void mma_f16(float& c0, float& c1, float& c2, float& c3,
                                        uint32_t a0, uint32_t a1, uint32_t a2, uint32_t a3,
                                        uint32_t b0, uint32_t b1) {
    asm volatile(
        "mma.sync.aligned.m16n8k16.row.col.f32.f16.f16.f32 "
        "{%0,%1,%2,%3}, {%4,%5,%6,%7}, {%8,%9}, {%0,%1,%2,%3};\n"
        : "+f"(c0), "+f"(c1), "+f"(c2), "+f"(c3)
        : "r"(a0), "r"(a1), "r"(a2), "r"(a3), "r"(b0), "r"(b1));
}
__device__ __forceinline__ void ldsm_x4(uint32_t& r0, uint32_t& r1, uint32_t& r2, uint32_t& r3,
                                        uint32_t addr) {
    asm volatile("ldmatrix.sync.aligned.m8n8.x4.shared.b16 {%0,%1,%2,%3}, [%4];"
                 : "=r"(r0), "=r"(r1), "=r"(r2), "=r"(r3) : "r"(addr));
}
__device__ __forceinline__ void ldsm_x2(uint32_t& r0, uint32_t& r1, uint32_t addr) {
    asm volatile("ldmatrix.sync.aligned.m8n8.x2.shared.b16 {%0,%1}, [%2];"
                 : "=r"(r0), "=r"(r1) : "r"(addr));
}
__device__ __forceinline__ void ldsm_x2_trans(uint32_t& b0, uint32_t& b1, uint32_t addr) {
    asm volatile("ldmatrix.sync.aligned.m8n8.x2.trans.shared.b16 {%0,%1}, [%2];"
                 : "=r"(b0), "=r"(b1) : "r"(addr));
}
__device__ __forceinline__ uint32_t packh2(float a, float b) {
    __half2 h = __floats2half2_rn(a, b);
    return *(uint32_t*)&h;
}

// ---------------- f32 -> f16 packers ----------------
__device__ __forceinline__ void pack8(const float* in, __half* out) {
    float4 a = *(const float4*)(in);
    float4 b = *(const float4*)(in + 4);
    uint4 o;
    o.x = packh2(a.x, a.y); o.y = packh2(a.z, a.w);
    o.z = packh2(b.x, b.y); o.w = packh2(b.z, b.w);
    *(uint4*)(out) = o;
}
__global__ void pack_h(const float* __restrict__ in, __half* __restrict__ out, int n)
{
    int i = (blockIdx.x * 256 + threadIdx.x) * 8;
    if (i < n) pack8(in + i, out + i);
}
// fused pack of ALL weights — segment END boundaries in 8-elem units
#define PW_Q   131072
#define PW_K   262144
#define PW_V   393216
#define PW_O   524288
#define PW_1   1048576
#define PW_AD  1081344
#define PW_2   1605632
#define PW_TOT 1638400
__global__ void pack_weights(const float* __restrict__ Wq, const float* __restrict__ Wk,
                             const float* __restrict__ Wv, const float* __restrict__ Wo,
                             const float* __restrict__ W1, const float* __restrict__ Wad,
                             const float* __restrict__ W2, const float* __restrict__ Wau,
                             __half* __restrict__ wqkv, __half* __restrict__ wo,
                             __half* __restrict__ w1c, __half* __restrict__ w2c)
{
    int u = blockIdx.x * 256 + threadIdx.x;
    if (u >= PW_TOT) return;
    if (u < PW_Q)       { int i = u*8;           pack8(Wq + i,  wqkv + i); }
    else if (u < PW_K)  { int i = (u-PW_Q)*8;    pack8(Wk + i,  wqkv + HH*HH + i); }
    else if (u < PW_V)  { int i = (u-PW_K)*8;    pack8(Wv + i,  wqkv + 2*HH*HH + i); }
    else if (u < PW_O)  { int i = (u-PW_V)*8;    pack8(Wo + i,  wo + i); }
    else if (u < PW_1)  { int i = (u-PW_O)*8;    pack8(W1 + i,  w1c + i); }
    else if (u < PW_AD) { int i = (u-PW_1)*8;    pack8(Wad + i, w1c + (size_t)FFF*HH + i); }
    else if (u < PW_2)  { int i = (u-PW_AD)*8;   int r = i / FFF, c = i - r*FFF;
                          pack8(W2 + i,  w2c + (size_t)r*FAK + c); }
    else                { int i = (u-PW_2)*8;    int r = i / ADD, c = i - r*ADD;
                          pack8(Wau + i, w2c + (size_t)r*FAK + FFF + c); }
}
// fused bias prep
__global__ void bias_prep(const float* __restrict__ bq, const float* __restrict__ bk,
                          const float* __restrict__ bv, const float* __restrict__ b2,
                          const float* __restrict__ bau, const float* __restrict__ b1,
                          const float* __restrict__ bad,
                          const float* __restrict__ Wg, const float* __restrict__ bg,
                          float* __restrict__ bqkv, float* __restrict__ b2c,
                          float* __restrict__ b1c, float* __restrict__ wgab)
{
    int i = blockIdx.x * 256 + threadIdx.x;
    if (i < HH)                 bqkv[i] = bq[i];
    else if (i < 2*HH)          bqkv[i] = bk[i - HH];
    else if (i < 3*HH)          bqkv[i] = bv[i - 2*HH];
    else if (i < 4*HH)          { int j = i - 3*HH; b2c[j] = b2[j] + bau[j]; }
    else if (i < 4*HH + FAK)    { int j = i - 4*HH;
                                  b1c[j] = (j < FFF) ? b1[j] : bad[j - FFF]; }
    else if (i < 4*HH+FAK+64)   { int d = i - 4*HH - FAK;
                                  wgab[d] = Wg[d] + Wg[64+d] + Wg[128+d] + Wg[192+d]; }
    else if (i < 4*HH+FAK+128)  { int d = i - 4*HH - FAK - 64;
                                  wgab[64+d] = Wg[256+d] + Wg[320+d] + Wg[384+d] + Wg[448+d]; }
    else if (i == 4*HH+FAK+128) wgab[128] = bg[0] + bg[1] + bg[2] + bg[3];
    else if (i == 4*HH+FAK+129) wgab[129] = bg[4] + bg[5] + bg[6] + bg[7];
}

// ================= fp16 mma.sync GEMM: 128x128, 4 warps (warp tile 64x64), 3-stage =================
#define HS_STRIDE 20
#define HS_AWORDS (128*HS_STRIDE)
#define HS_STAGEW (2*HS_AWORDS)
#define HS_BYTES  (3*HS_STAGEW*4)   // 61440

template<int EPI, int OUTH>   // EPI: 0=none,1=gelu,2=elu,3=mixed
__global__ void __launch_bounds__(128, 2) gemm_h(const __half* __restrict__ A,
                                                 const __half* __restrict__ W,
                                                 const float* __restrict__ bias,
                                                 void* __restrict__ C,
                                                 int M, int N, int K, int ldc)
{
    extern __shared__ uint32_t sm[];
    int tid  = threadIdx.x;
    int wid  = tid >> 5, lane = tid & 31;
    int wm   = wid >> 1;          // 0..1  (64 rows)
    int wn   = wid & 1;           // 0..1  (64 cols)
    int bm = blockIdx.y * 128, bn = blockIdx.x * 128;
    int r4 = lane >> 2;
    int c4 = lane & 3;
    bool elu_side = (EPI == 3) && (bn >= FFF);

    float acc[4][8][4];
    #pragma unroll
    for (int mt = 0; mt < 4; mt++)
        #pragma unroll
        for (int nt = 0; nt < 8; nt++)
            #pragma unroll
            for (int u = 0; u < 4; u++) acc[mt][nt][u] = 0.0f;

    // producer: thread t handles row t of A and row t of B (4 chunks each)
    const __half* aptr = A + (size_t)(bm + tid) * K;
    const __half* wptr = W + (size_t)(bn + tid) * K;
    uint32_t sb = smem_u32(sm);
    uint32_t sa_base = sb + (uint32_t)(tid * HS_STRIDE) * 4;
    uint32_t sb_base = sa_base + HS_AWORDS * 4;

    // consumer ldmatrix lane addresses (byte offsets within a stage)
    uint32_t aoff = (uint32_t)((wm * 64 + (lane & 15)) * HS_STRIDE) * 4 + (lane >> 4) * 16;
    uint32_t boff = (uint32_t)(HS_AWORDS * 4)
                  + (uint32_t)((wn * 64 + (lane & 7)) * HS_STRIDE) * 4 + ((lane >> 3) & 1) * 16;

    int T = K >> 5;

    // prologue: tiles 0,1 -> stages 0,1
    #pragma unroll
    for (int t0 = 0; t0 < 2; t0++) {
        const __half* ap = aptr + t0 * 32;
        const __half* wp = wptr + t0 * 32;
        uint32_t so = (uint32_t)(t0 * HS_STAGEW) * 4;
        #pragma unroll
        for (int i = 0; i < 4; i++) {
            cp16(sa_base + so + i * 16, ap + i * 8);
            cp16(sb_base + so + i * 16, wp + i * 8);
        }
        CP_COMMIT();
    }

    int stage = 0;
    for (int k0 = 0; k0 < T; k0++) {
        if (k0 + 1 < T) { CP_WAIT(1); } else { CP_WAIT(0); }
        __syncthreads();
        if (k0 + 2 < T) {
            int ns = stage + 2; if (ns >= 3) ns -= 3;
            const __half* ap = aptr + (k0 + 2) * 32;
            const __half* wp = wptr + (k0 + 2) * 32;
            uint32_t so = (uint32_t)(ns * HS_STAGEW) * 4;
            #pragma unroll
            for (int i = 0; i < 4; i++) {
                cp16(sa_base + so + i * 16, ap + i * 8);
                cp16(sb_base + so + i * 16, wp + i * 8);
            }
            CP_COMMIT();
        }
        uint32_t stg = sb + (uint32_t)(stage * HS_STAGEW) * 4;
        #pragma unroll
        for (int ks = 0; ks < 2; ks++) {
            uint32_t af[4][4];
            #pragma unroll
            for (int mt = 0; mt < 4; mt++)
                ldsm_x4(af[mt][0], af[mt][1], af[mt][2], af[mt][3],
                        stg + aoff + (uint32_t)(mt * 16 * HS_STRIDE) * 4 + ks * 32);
            uint32_t bf[8][2];
            #pragma unroll
            for (int nt = 0; nt < 8; nt++)
                ldsm_x2(bf[nt][0], bf[nt][1],
                        stg + boff + (uint32_t)(nt * 8 * HS_STRIDE) * 4 + ks * 32);
            #pragma unroll
            for (int mt = 0; mt < 4; mt++)
                #pragma unroll
                for (int nt = 0; nt < 8; nt++)
                    mma_f16(acc[mt][nt][0], acc[mt][nt][1], acc[mt][nt][2], acc[mt][nt][3],
                            af[mt][0], af[mt][1], af[mt][2], af[mt][3],
                            bf[nt][0], bf[nt][1]);
        }
        stage++; if (stage == 3) stage = 0;
    }

    // ---- epilogue ----
    #pragma unroll
    for (int mt = 0; mt < 4; mt++) {
        int gr = bm + wm * 64 + mt * 16 + r4;
        #pragma unroll
        for (int nt = 0; nt < 8; nt++) {
            int gc = bn + wn * 64 + nt * 8 + c4 * 2;
            float b0 = bias[gc], b1 = bias[gc + 1];
            float v[4];
            v[0] = acc[mt][nt][0] + b0;
            v[1] = acc[mt][nt][1] + b1;
            v[2] = acc[mt][nt][2] + b0;
            v[3] = acc[mt][nt][3] + b1;
            #pragma unroll
            for (int u = 0; u < 4; u++) {
                if (EPI == 1) v[u] = 0.5f * v[u] * (1.0f + erff(v[u] * 0.7071067811865476f));
                else if (EPI == 2) v[u] = v[u] > 0.0f ? v[u] : expm1f(v[u]);
                else if (EPI == 3) {
                    if (elu_side) v[u] = v[u] > 0.0f ? v[u] : expm1f(v[u]);
                    else v[u] = 0.5f * v[u] * (1.0f + erff(v[u] * 0.7071067811865476f));
                }
            }
            if (OUTH) {
                __half* Ch = (__half*)C;
                *(uint32_t*)(Ch + (size_t)gr * ldc + gc)       = packh2(v[0], v[1]);
                *(uint32_t*)(Ch + (size_t)(gr + 8) * ldc + gc) = packh2(v[2], v[3]);
            } else {
                float* Cf = (float*)C;
                *(float2*)(Cf + (size_t)gr * ldc + gc)       = make_float2(v[0], v[1]);
                *(float2*)(Cf + (size_t)(gr + 8) * ldc + gc) = make_float2(v[2], v[3]);
            }
        }
    }
}

// ---------------- relative position bias table ----------------
__global__ void pbias_kernel(const float* __restrict__ rel_embed, float* __restrict__ pb)
{
    int d = blockIdx.x * blockDim.x + threadIdx.x;
    if (d >= 2047) return;
    int rel = d - 1023;
    int bucket = (rel > 0) ? 160 : 0;
    int r = rel < 0 ? -rel : rel;
    int val;
    if (r < 80) {
        val = r;
    } else {
        float rf = (float)(r < 1 ? 1 : r);
        float t = logf(rf / 80.0f) / 2.3025851f * 80.0f;
        int large = 80 + (int)t;
        val = large < 159 ? large : 159;
    }
    bucket += val;
    #pragma unroll
    for (int h = 0; h < NHH; h++)
        pb[h * 2048 + d] = rel_embed[bucket * NHH + h];
}

// ---------------- gate kernel v2 ----------------
#define GXS 1088
__global__ void __launch_bounds__(256) gate_kernel(const float* __restrict__ x,
                                                   const float* __restrict__ wgab,
                                                   const float* __restrict__ gc,
                                                   float* __restrict__ gate)
{
    __shared__ float xs[8 * GXS];
    __shared__ float wg[130];
    int tid = threadIdx.x;
    int bs0 = blockIdx.x * 8;
    if (tid < 130) wg[tid] = wgab[tid];
    for (int idx = tid; idx < 8 * 1024; idx += 256) {
        int r = idx >> 10, i = idx & 1023;
        int d = i & 63, h = i >> 6;
        xs[r * GXS + d * 17 + h] = x[(size_t)(bs0 + r) * HH + i];
    }
    __syncthreads();
    int w = tid >> 5, lane = tid & 31;
    int h = lane >> 1, ab = lane & 1;
    float acc = wg[128 + ab];
    const float* xr = xs + w * GXS + h;
    const float* wp = wg + ab * 64;
    #pragma unroll 16
    for (int d = 0; d < 64; d++) acc += xr[d * 17] * wp[d];
    float other = __shfl_xor_sync(0xffffffffu, acc, 1);
    if (ab == 0) {
        float ga = 1.0f / (1.0f + expf(-acc));
        float gb = 1.0f / (1.0f + expf(-other));
        float go = ga * (gb * gc[h] - 1.0f) + 2.0f;
        int bs = bs0 + w;
        int b = bs >> 10, s = bs & 1023;
        gate[(b * NHH + h) * SS + s] = go;
    }
}

// ================= fp16 tensor-core flash attention (2-stage KV pipeline) =================
#define AS 36
#define ATT_WORDS (6*64*AS)
#define ATT_BYTES (ATT_WORDS*4)    // 55296

__global__ void __launch_bounds__(128, 3) attn_tc(const __half* __restrict__ qkv,
                                                  const float* __restrict__ gate,
                                                  const float* __restrict__ pb,
                                                  __half* __restrict__ ctx)
{
    extern __shared__ uint32_t as_[];
    uint32_t* Qs = as_;
    uint32_t* Ps = as_ + 5 * 64 * AS;

    int tid = threadIdx.x, wid = tid >> 5, lane = tid & 31;
    int r4 = lane >> 2, c4 = lane & 3;
    int i0 = blockIdx.x * 64, h = blockIdx.y, b = blockIdx.z;

    const __half* qb = qkv + ((size_t)(b * SS + i0)) * QKVN + h * HDD;
    const __half* kb = qkv + ((size_t)(b * SS)) * QKVN + HH + h * HDD;
    const __half* vb = qkv + ((size_t)(b * SS)) * QKVN + 2 * HH + h * HDD;

    uint32_t ks_sm[2] = { smem_u32(as_ + 1 * 64 * AS), smem_u32(as_ + 2 * 64 * AS) };
    uint32_t vs_sm[2] = { smem_u32(as_ + 3 * 64 * AS), smem_u32(as_ + 4 * 64 * AS) };

    for (int idx = tid; idx < 64 * 8; idx += 128) {
        int r = idx >> 3, cc = idx & 7;
        cp16(ks_sm[0] + (uint32_t)(r * AS + cc * 4) * 4, kb + (size_t)r * QKVN + cc * 8);
        cp16(vs_sm[0] + (uint32_t)(r * AS + cc * 4) * 4, vb + (size_t)r * QKVN + cc * 8);
    }
    CP_COMMIT();

    for (int idx = tid; idx < 64 * 8; idx += 128) {
        int r = idx >> 3, cc = idx & 7;
        *(uint4*)(Qs + r * AS + cc * 4) = *(const uint4*)(qb + (size_t)r * QKVN + cc * 8);
    }
    __syncthreads();

    uint32_t qf[4][4];
    {
        const uint32_t* qp = Qs + (wid * 16 + r4) * AS + c4;
        #pragma unroll
        for (int ks = 0; ks < 4; ks++) {
            qf[ks][0] = qp[ks * 8];
            qf[ks][1] = qp[8 * AS + ks * 8];
            qf[ks][2] = qp[ks * 8 + 4];
            qf[ks][3] = qp[8 * AS + ks * 8 + 4];
        }
    }

    float gate0 = gate[(b * NHH + h) * SS + i0 + wid * 16 + r4];
    float gate1 = gate[(b * NHH + h) * SS + i0 + wid * 16 + r4 + 8];
    const float* pbh = pb + h * 2048 + 1023 - (i0 + wid * 16 + r4);

    float m0 = -INFINITY, m1 = -INFINITY, l0 = 0.0f, l1 = 0.0f;
    float oa[8][4];
    #pragma unroll
    for (int nt = 0; nt < 8; nt++)
        #pragma unroll
        for (int u = 0; u < 4; u++) oa[nt][u] = 0.0f;

    for (int jt = 0; jt < SS / 64; jt++) {
        int st = jt & 1;
        if (jt + 1 < SS / 64) {
            __syncthreads();
            int j1 = (jt + 1) * 64;
            for (int idx = tid; idx < 64 * 8; idx += 128) {
                int r = idx >> 3, cc = idx & 7;
                cp16(ks_sm[st ^ 1] + (uint32_t)(r * AS + cc * 4) * 4,
                     kb + (size_t)(j1 + r) * QKVN + cc * 8);
                cp16(vs_sm[st ^ 1] + (uint32_t)(r * AS + cc * 4) * 4,
                     vb + (size_t)(j1 + r) * QKVN + cc * 8);
            }
            CP_COMMIT();
            CP_WAIT(1);
        } else {
            CP_WAIT(0);
        }
        __syncthreads();

        const uint32_t* Kp = as_ + (1 + st) * 64 * AS;
        uint32_t vls = vs_sm[st] + (uint32_t)(lane & 15) * AS * 4;
        int j0 = jt * 64;

        float sf[8][4];
        #pragma unroll
        for (int nt = 0; nt < 8; nt++)
            #pragma unroll
            for (int u = 0; u < 4; u++) sf[nt][u] = 0.0f;
        #pragma unroll
        for (int ks = 0; ks < 4; ks++) {
            #pragma unroll
            for (int nt = 0; nt < 8; nt++) {
                const uint32_t* p = Kp + (nt * 8 + r4) * AS + ks * 8 + c4;
                mma_f16(sf[nt][0], sf[nt][1], sf[nt][2], sf[nt][3],
                        qf[ks][0], qf[ks][1], qf[ks][2], qf[ks][3],
                        p[0], p[4]);
            }
        }

        #pragma unroll
        for (int nt = 0; nt < 8; nt++) {
            int j = j0 + nt * 8 + 2 * c4;
            float pb0 = pbh[j];
            float pb1 = pbh[j + 1];
            float pb2 = pbh[j - 8];
            float pb3 = pbh[j - 7];
            sf[nt][0] = sf[nt][0] * 0.125f + gate0 * pb0;
            sf[nt][1] = sf[nt][1] * 0.125f + gate0 * pb1;
            sf[nt][2] = sf[nt][2] * 0.125f + gate1 * pb2;
            sf[nt][3] = sf[nt][3] * 0.125f + gate1 * pb3;
        }

        float mx0 = -INFINITY, mx1 = -INFINITY;
        #pragma unroll
        for (int nt = 0; nt < 8; nt++) {
            mx0 = fmaxf(mx0, fmaxf(sf[nt][0], sf[nt][1]));
            mx1 = fmaxf(mx1, fmaxf(sf[nt][2], sf[nt][3]));
        }
        mx0 = fmaxf(mx0, __shfl_xor_sync(0xffffffffu, mx0, 1));
        mx0 = fmaxf(mx0, __shfl_xor_sync(0xffffffffu, mx0, 2));
        mx1 = fmaxf(mx1, __shfl_xor_sync(0xffffffffu, mx1, 1));
        mx1 = fmaxf(mx1, __shfl_xor_sync(0xffffffffu, mx1, 2));
        float mn0 = fmaxf(m0, mx0), mn1 = fmaxf(m1, mx1);
        float a0 = __expf(m0 - mn0), a1 = __expf(m1 - mn1);

        float ls0 = 0.0f, ls1 = 0.0f;
        uint32_t* pr0 = Ps + (wid * 16 + r4) * AS + c4;
        uint32_t* pr1 = pr0 + 8 * AS;
        #pragma unroll
        for (int nt = 0; nt < 8; nt++) {
            float p0 = __expf(sf[nt][0] - mn0);
            float p1 = __expf(sf[nt][1] - mn0);
            float p2 = __expf(sf[nt][2] - mn1);
            float p3 = __expf(sf[nt][3] - mn1);
            ls0 += p0 + p1; ls1 += p2 + p3;
            pr0[nt * 4] = packh2(p0, p1);
            pr1[nt * 4] = packh2(p2, p3);
        }
        ls0 += __shfl_xor_sync(0xffffffffu, ls0, 1);
        ls0 += __shfl_xor_sync(0xffffffffu, ls0, 2);
        ls1 += __shfl_xor_sync(0xffffffffu, ls1, 1);
        ls1 += __shfl_xor_sync(0xffffffffu, ls1, 2);
        l0 = l0 * a0 + ls0;  l1 = l1 * a1 + ls1;
        m0 = mn0;  m1 = mn1;
        #pragma unroll
        for (int nt = 0; nt < 8; nt++) {
            oa[nt][0] *= a0; oa[nt][1] *= a0;
            oa[nt][2] *= a1; oa[nt][3] *= a1;
        }
        __syncwarp();

        const uint32_t* pp = Ps + (wid * 16 + r4) * AS + c4;
        #pragma unroll
        for (int ks = 0; ks < 4; ks++) {
            uint32_t af0 = pp[ks * 8];
            uint32_t af1 = pp[8 * AS + ks * 8];
            uint32_t af2 = pp[ks * 8 + 4];
            uint32_t af3 = pp[8 * AS + ks * 8 + 4];
            uint32_t vrow = vls + (uint32_t)(ks * 16) * AS * 4;
            #pragma unroll
            for (int nt = 0; nt < 8; nt++) {
                uint32_t b0, b1;
                ldsm_x2_trans(b0, b1, vrow + nt * 16);
                mma_f16(oa[nt][0], oa[nt][1], oa[nt][2], oa[nt][3],
                        af0, af1, af2, af3, b0, b1);
            }
        }
    }

    float inv0 = 1.0f / l0, inv1 = 1.0f / l1;
    __half* cb0 = ctx + ((size_t)(b * SS + i0 + wid * 16 + r4)) * HH + h * HDD;
    __half* cb1 = cb0 + 8 * HH;
    #pragma unroll
    for (int nt = 0; nt < 8; nt++) {
        *(uint32_t*)(cb0 + nt * 8 + 2 * c4) = packh2(oa[nt][0] * inv0, oa[nt][1] * inv0);
        *(uint32_t*)(cb1 + nt * 8 + 2 * c4) = packh2(oa[nt][2] * inv1, oa[nt][3] * inv1);
    }
}

// ---------------- residual-add + LayerNorm (+ optional half copy) ----------------
__global__ void ln_kernel(const float* __restrict__ A, const float* __restrict__ B,
                          const float* __restrict__ g, const float* __restrict__ bt,
                          float* __restrict__ out, __half* __restrict__ out2)
{
    __shared__ float sm[8];
    int row = blockIdx.x;
    int t = threadIdx.x;
    size_t base = (size_t)row * HH;
    float vals[4];
    #pragma unroll
    for (int u = 0; u < 4; u++) {
        int i = t + u*256;
        vals[u] = A[base + i] + B[base + i];
    }
    float sum = vals[0] + vals[1] + vals[2] + vals[3];
    #pragma unroll
    for (int off = 16; off >= 1; off >>= 1) sum += __shfl_xor_sync(0xffffffffu, sum, off);
    if ((t & 31) == 0) sm[t >> 5] = sum;
    __syncthreads();
    float tot = 0.0f;
    #pragma unroll
    for (int w = 0; w < 8; w++) tot += sm[w];
    float mean = tot * (1.0f / HH);
    __syncthreads();
    float vs = 0.0f;
    #pragma unroll
    for (int u = 0; u < 4; u++) { float d = vals[u] - mean; vs += d * d; }
    #pragma unroll
    for (int off = 16; off >= 1; off >>= 1) vs += __shfl_xor_sync(0xffffffffu, vs, off);
    if ((t & 31) == 0) sm[t >> 5] = vs;
    __syncthreads();
    float vtot = 0.0f;
    #pragma unroll
    for (int w = 0; w < 8; w++) vtot += sm[w];
    float rstd = rsqrtf(vtot * (1.0f / HH) + EPSF);
    #pragma unroll
    for (int u = 0; u < 4; u++) {
        int i = t + u*256;
        float r = (vals[u] - mean) * rstd * g[i] + bt[i];
        out[base + i] = r;
        if (out2) out2[base + i] = __float2half_rn(r);
    }
}

// ---------------- launch ----------------
extern "C" void kernel_launch(void* const* d_in, const int* in_sizes, int n_in,
                              void* d_out, int out_size)
{
    const float* x   = (const float*)d_in[0];
    const float* Wq  = (const float*)d_in[1];
    const float* bq  = (const float*)d_in[2];
    const float* Wk  = (const float*)d_in[3];
    const float* bk  = (const float*)d_in[4];
    const float* Wv  = (const float*)d_in[5];
    const float* bv  = (const float*)d_in[6];
    const float* Wo  = (const float*)d_in[7];
    const float* bo  = (const float*)d_in[8];
    const float* Wg  = (const float*)d_in[9];
    const float* bg  = (const float*)d_in[10];
    const float* gru = (const float*)d_in[11];
    const float* rel = (const float*)d_in[12];
    const float* l1g = (const float*)d_in[13];
    const float* l1b = (const float*)d_in[14];
    const float* W1  = (const float*)d_in[15];
    const float* b1  = (const float*)d_in[16];
    const float* W2  = (const float*)d_in[17];
    const float* b2  = (const float*)d_in[18];
    const float* l2g = (const float*)d_in[19];
    const float* l2b = (const float*)d_in[20];
    const float* Wad = (const float*)d_in[21];
    const float* bad = (const float*)d_in[22];
    const float* Wau = (const float*)d_in[23];
    const float* bau = (const float*)d_in[24];
    float* out = (float*)d_out;

    __half *pqkv, *pctx, *phr, *pff1, *pxr, *pwqkv, *pwo, *pw1c, *pw2c;
    float *patt, *ph, *pff2, *pgate, *ppb, *pbqkv, *pb2c, *pb1c, *pwgab;
    cudaGetSymbolAddress((void**)&pqkv, g_qkv);
    cudaGetSymbolAddress((void**)&pctx, g_ctx);
    cudaGetSymbolAddress((void**)&patt, g_att);
    cudaGetSymbolAddress((void**)&ph,   g_h);
    cudaGetSymbolAddress((void**)&phr,  g_hr);
    cudaGetSymbolAddress((void**)&pff1, g_ff1);
    cudaGetSymbolAddress((void**)&pff2, g_ff2);
    cudaGetSymbolAddress((void**)&pgate, g_gate);
    cudaGetSymbolAddress((void**)&ppb,  g_pb);
    cudaGetSymbolAddress((void**)&pxr,  g_xr);
    cudaGetSymbolAddress((void**)&pwqkv, g_wqkv);
    cudaGetSymbolAddress((void**)&pwo,  g_wo);
    cudaGetSymbolAddress((void**)&pw1c, g_w1c);
    cudaGetSymbolAddress((void**)&pw2c, g_w2c);
    cudaGetSymbolAddress((void**)&pbqkv, g_bqkv);
    cudaGetSymbolAddress((void**)&pb2c, g_b2c);
    cudaGetSymbolAddress((void**)&pb1c, g_b1c);
    cudaGetSymbolAddress((void**)&pwgab, g_wgab);

    cudaFuncSetAttribute(gemm_h<0,0>, cudaFuncAttributeMaxDynamicSharedMemorySize, HS_BYTES);
    cudaFuncSetAttribute(gemm_h<0,1>, cudaFuncAttributeMaxDynamicSharedMemorySize, HS_BYTES);
    cudaFuncSetAttribute(gemm_h<3,1>, cudaFuncAttributeMaxDynamicSharedMemorySize, HS_BYTES);
    cudaFuncSetAttribute(attn_tc, cudaFuncAttributeMaxDynamicSharedMemorySize, ATT_BYTES);

    // launches 1-3
    pack_weights<<<(PW_TOT + 255)/256, 256>>>(Wq, Wk, Wv, Wo, W1, Wad, W2, Wau,
                                              pwqkv, pwo, pw1c, pw2c);
    pack_h<<<(MM*HH)/2048, 256>>>(x, pxr, MM*HH);
    bias_prep<<<(4*HH + FAK + 130 + 255)/256, 256>>>(bq, bk, bv, b2, bau, b1, bad,
                                                     Wg, bg, pbqkv, pb2c, pb1c, pwgab);
    // 4) fused QKV projection  (ncu capture target)
    gemm_h<0,1><<<dim3(QKVN/128, MM/128), 128, HS_BYTES>>>(pxr, pwqkv, pbqkv, pqkv, MM, QKVN, HH, QKVN);
    // 5-6) pos bias + gates
    pbias_kernel<<<(2047 + 127) / 128, 128>>>(rel, ppb);
    gate_kernel<<<MM/8, 256>>>(x, pwgab, gru, pgate);
    // 7) attention
    attn_tc<<<dim3(SS/64, NHH, BB), 128, ATT_BYTES>>>(pqkv, pgate, ppb, pctx);
    // 8) output projection (float out)
    gemm_h<0,0><<<dim3(HH/128, MM/128), 128, HS_BYTES>>>(pctx, pwo, bo, patt, MM, HH, HH, HH);
    // 9) residual + LN1
    ln_kernel<<<MM, 256>>>(x, patt, l1g, l1b, ph, phr);
    // 10) fused FFN-up(gelu) + adapter-down(elu)
    gemm_h<3,1><<<dim3(FAK/128, MM/128), 128, HS_BYTES>>>(phr, pw1c, pb1c, pff1, MM, FAK, HH, FAK);
    // 11) fused FFN-down + adapter-up
    gemm_h<0,0><<<dim3(HH/128, MM/128), 128, HS_BYTES>>>(pff1, pw2c, pb2c, pff2, MM, HH, FAK, HH);
    // 12) h + (ff+adapt), LN2 -> out
    ln_kernel<<<MM, 256>>>(ph, pff2, l2g, l2b, out, nullptr);
}

// round 14
// speedup vs baseline: 1.3522x; 1.3522x over previous
#include <cuda_runtime.h>
#include <cuda_fp16.h>
#include <math.h>
#include <stdint.h>

// ---------------- problem constants ----------------
#define BB   4
#define SS   1024
#define HH   1024
#define NHH  16
#define HDD  64
#define FFF  4096
#define ADD  256
#define MM   (BB*SS)          // 4096 rows
#define EPSF 1e-5f
#define QKVN 3072
#define FAK  (FFF+ADD)        // 4352

// ---------------- scratch ----------------
__device__ __half g_qkv [(size_t)MM*QKVN];
__device__ __half g_ctx [MM*HH];
__device__ float  g_att [MM*HH];
__device__ float  g_h   [MM*HH];
__device__ __half g_hr  [MM*HH];
__device__ __half g_ff1 [(size_t)MM*FAK];
__device__ float  g_ff2 [MM*HH];
__device__ float  g_gate[BB*NHH*SS];
__device__ float  g_pb  [NHH*2048];
// fp16 operand copies
__device__ __half g_xr  [MM*HH];
__device__ __half g_wqkv[QKVN*HH];
__device__ __half g_wo  [HH*HH];
__device__ __half g_w1c [(size_t)FAK*HH];
__device__ __half g_w2c [(size_t)HH*FAK];
__device__ float  g_bqkv[QKVN];
__device__ float  g_b2c [HH];
__device__ float  g_b1c [FAK];
__device__ float  g_wgab[130];

// ---------------- helpers ----------------
__device__ __forceinline__ uint32_t smem_u32(const void* p) {
    uint32_t a;
    asm("{ .reg .u64 t; cvta.to.shared.u64 t, %1; cvt.u32.u64 %0, t; }" : "=r"(a) : "l"(p));
    return a;
}
__device__ __forceinline__ void cp16(uint32_t s, const void* g) {
    asm volatile("cp.async.cg.shared.global [%0], [%1], 16;" :: "r"(s), "l"(g));
}
#define CP_COMMIT() asm volatile("cp.async.commit_group;")
#define CP_WAIT(N)  asm volatile("cp.async.wait_group %0;" :: "n"(N))

__device__ __forceinline__ void mma_f16(float& c0, float& c1, float& c2, float& c3,
                                        uint32_t a0, uint32_t a1, uint32_t a2, uint32_t a3,
                                        uint32_t b0, uint32_t b1) {
    asm volatile(
        "mma.sync.aligned.m16n8k16.row.col.f32.f16.f16.f32 "
        "{%0,%1,%2,%3}, {%4,%5,%6,%7}, {%8,%9}, {%0,%1,%2,%3};\n"
        : "+f"(c0), "+f"(c1), "+f"(c2), "+f"(c3)
        : "r"(a0), "r"(a1), "r"(a2), "r"(a3), "r"(b0), "r"(b1));
}
__device__ __forceinline__ void ldsm_x4(uint32_t& r0, uint32_t& r1, uint32_t& r2, uint32_t& r3,
                                        uint32_t addr) {
    asm volatile("ldmatrix.sync.aligned.m8n8.x4.shared.b16 {%0,%1,%2,%3}, [%4];"
                 : "=r"(r0), "=r"(r1), "=r"(r2), "=r"(r3) : "r"(addr));
}
__device__ __forceinline__ void ldsm_x2(uint32_t& r0, uint32_t& r1, uint32_t addr) {
    asm volatile("ldmatrix.sync.aligned.m8n8.x2.shared.b16 {%0,%1}, [%2];"
                 : "=r"(r0), "=r"(r1) : "r"(addr));
}
__device__ __forceinline__ void ldsm_x2_trans(uint32_t& b0, uint32_t& b1, uint32_t addr) {
    asm volatile("ldmatrix.sync.aligned.m8n8.x2.trans.shared.b16 {%0,%1}, [%2];"
                 : "=r"(b0), "=r"(b1) : "r"(addr));
}
__device__ __forceinline__ uint32_t packh2(float a, float b) {
    __half2 h = __floats2half2_rn(a, b);
    return *(uint32_t*)&h;
}

// ---------------- f32 -> f16 packers ----------------
__device__ __forceinline__ void pack8(const float* in, __half* out) {
    float4 a = *(const float4*)(in);
    float4 b = *(const float4*)(in + 4);
    uint4 o;
    o.x = packh2(a.x, a.y); o.y = packh2(a.z, a.w);
    o.z = packh2(b.x, b.y); o.w = packh2(b.z, b.w);
    *(uint4*)(out) = o;
}
__global__ void pack_h(const float* __restrict__ in, __half* __restrict__ out, int n)
{
    int i = (blockIdx.x * 256 + threadIdx.x) * 8;
    if (i < n) pack8(in + i, out + i);
}
// fused pack of ALL weights — segment END boundaries in 8-elem units
#define PW_Q   131072
#define PW_K   262144
#define PW_V   393216
#define PW_O   524288
#define PW_1   1048576
#define PW_AD  1081344
#define PW_2   1605632
#define PW_TOT 1638400
__global__ void pack_weights(const float* __restrict__ Wq, const float* __restrict__ Wk,
                             const float* __restrict__ Wv, const float* __restrict__ Wo,
                             const float* __restrict__ W1, const float* __restrict__ Wad,
                             const float* __restrict__ W2, const float* __restrict__ Wau,
                             __half* __restrict__ wqkv, __half* __restrict__ wo,
                             __half* __restrict__ w1c, __half* __restrict__ w2c)
{
    int u = blockIdx.x * 256 + threadIdx.x;
    if (u >= PW_TOT) return;
    if (u < PW_Q)       { int i = u*8;           pack8(Wq + i,  wqkv + i); }
    else if (u < PW_K)  { int i = (u-PW_Q)*8;    pack8(Wk + i,  wqkv + HH*HH + i); }
    else if (u < PW_V)  { int i = (u-PW_K)*8;    pack8(Wv + i,  wqkv + 2*HH*HH + i); }
    else if (u < PW_O)  { int i = (u-PW_V)*8;    pack8(Wo + i,  wo + i); }
    else if (u < PW_1)  { int i = (u-PW_O)*8;    pack8(W1 + i,  w1c + i); }
    else if (u < PW_AD) { int i = (u-PW_1)*8;    pack8(Wad + i, w1c + (size_t)FFF*HH + i); }
    else if (u < PW_2)  { int i = (u-PW_AD)*8;   int r = i / FFF, c = i - r*FFF;
                          pack8(W2 + i,  w2c + (size_t)r*FAK + c); }
    else                { int i = (u-PW_2)*8;    int r = i / ADD, c = i - r*ADD;
                          pack8(Wau + i, w2c + (size_t)r*FAK + FFF + c); }
}
// fused bias prep
__global__ void bias_prep(const float* __restrict__ bq, const float* __restrict__ bk,
                          const float* __restrict__ bv, const float* __restrict__ b2,
                          const float* __restrict__ bau, const float* __restrict__ b1,
                          const float* __restrict__ bad,
                          const float* __restrict__ Wg, const float* __restrict__ bg,
                          float* __restrict__ bqkv, float* __restrict__ b2c,
                          float* __restrict__ b1c, float* __restrict__ wgab)
{
    int i = blockIdx.x * 256 + threadIdx.x;
    if (i < HH)                 bqkv[i] = bq[i];
    else if (i < 2*HH)          bqkv[i] = bk[i - HH];
    else if (i < 3*HH)          bqkv[i] = bv[i - 2*HH];
    else if (i < 4*HH)          { int j = i - 3*HH; b2c[j] = b2[j] + bau[j]; }
    else if (i < 4*HH + FAK)    { int j = i - 4*HH;
                                  b1c[j] = (j < FFF) ? b1[j] : bad[j - FFF]; }
    else if (i < 4*HH+FAK+64)   { int d = i - 4*HH - FAK;
                                  wgab[d] = Wg[d] + Wg[64+d] + Wg[128+d] + Wg[192+d]; }
    else if (i < 4*HH+FAK+128)  { int d = i - 4*HH - FAK - 64;
                                  wgab[64+d] = Wg[256+d] + Wg[320+d] + Wg[384+d] + Wg[448+d]; }
    else if (i == 4*HH+FAK+128) wgab[128] = bg[0] + bg[1] + bg[2] + bg[3];
    else if (i == 4*HH+FAK+129) wgab[129] = bg[4] + bg[5] + bg[6] + bg[7];
}

// ================= fp16 mma.sync GEMM (128x128, 8 warps, ldmatrix, 4-stage) =================
#define HS_STRIDE 20
#define HS_AWORDS (128*HS_STRIDE)
#define HS_STAGEW (2*HS_AWORDS)
#define HS_BYTES  (4*HS_STAGEW*4)   // 81920

template<int EPI, int OUTH>   // EPI: 0=none,1=gelu,2=elu,3=mixed
__global__ void __launch_bounds__(256, 2) gemm_h(const __half* __restrict__ A,
                                                 const __half* __restrict__ W,
                                                 const float* __restrict__ bias,
                                                 void* __restrict__ C,
                                                 int M, int N, int K, int ldc)
{
    extern __shared__ uint32_t sm[];
    int tid  = threadIdx.x;
    int wid  = tid >> 5, lane = tid & 31;
    int wm   = wid >> 2;          // 0..1
    int wn   = wid & 3;           // 0..3
    int bm = blockIdx.y * 128, bn = blockIdx.x * 128;
    int r4 = lane >> 2;
    int c4 = lane & 3;
    bool elu_side = (EPI == 3) && (bn >= FFF);

    float acc[4][4][4];
    #pragma unroll
    for (int mt = 0; mt < 4; mt++)
        #pragma unroll
        for (int nt = 0; nt < 4; nt++)
            #pragma unroll
            for (int u = 0; u < 4; u++) acc[mt][nt][u] = 0.0f;

    int lrow = tid >> 2;            // 0..63
    int lcc  = tid & 3;             // 16B chunk
    const __half* aptr = A + (size_t)(bm + lrow) * K + lcc * 8;
    const __half* wptr = W + (size_t)(bn + lrow) * K + lcc * 8;
    uint32_t sb = smem_u32(sm);
    uint32_t sa_base = sb + (uint32_t)(lrow * HS_STRIDE + lcc * 4) * 4;

    uint32_t aoff = (uint32_t)((wm * 64 + (lane & 15)) * HS_STRIDE) * 4 + (lane >> 4) * 16;
    uint32_t boff = (uint32_t)(HS_AWORDS * 4)
                  + (uint32_t)((wn * 32 + (lane & 7)) * HS_STRIDE) * 4 + ((lane >> 3) & 1) * 16;

    int T = K >> 5;

    // prologue: tiles 0,1,2 -> stages 0,1,2
    #pragma unroll
    for (int t0 = 0; t0 < 3; t0++) {
        const __half* ap = aptr + t0 * 32;
        const __half* wp = wptr + t0 * 32;
        uint32_t so = sa_base + (uint32_t)(t0 * HS_STAGEW) * 4;
        #pragma unroll
        for (int i = 0; i < 2; i++) {
            cp16(so + (uint32_t)(i * 64 * HS_STRIDE) * 4, ap + (size_t)(i * 64) * K);
            cp16(so + (uint32_t)(HS_AWORDS + i * 64 * HS_STRIDE) * 4, wp + (size_t)(i * 64) * K);
        }
        CP_COMMIT();
    }

    for (int k0 = 0; k0 < T; k0++) {
        int stage = k0 & 3;
        if (k0 + 2 < T)      { CP_WAIT(2); }
        else if (k0 + 1 < T) { CP_WAIT(1); }
        else                 { CP_WAIT(0); }
        __syncthreads();
        if (k0 + 3 < T) {
            int ns = (k0 + 3) & 3;
            const __half* ap = aptr + (k0 + 3) * 32;
            const __half* wp = wptr + (k0 + 3) * 32;
            uint32_t so = sa_base + (uint32_t)(ns * HS_STAGEW) * 4;
            #pragma unroll
            for (int i = 0; i < 2; i++) {
                cp16(so + (uint32_t)(i * 64 * HS_STRIDE) * 4, ap + (size_t)(i * 64) * K);
                cp16(so + (uint32_t)(HS_AWORDS + i * 64 * HS_STRIDE) * 4, wp + (size_t)(i * 64) * K);
            }
            CP_COMMIT();
        }
        uint32_t stg = sb + (uint32_t)(stage * HS_STAGEW) * 4;
        #pragma unroll
        for (int ks = 0; ks < 2; ks++) {
            uint32_t af[4][4];
            #pragma unroll
            for (int mt = 0; mt < 4; mt++)
                ldsm_x4(af[mt][0], af[mt][1], af[mt][2], af[mt][3],
                        stg + aoff + (uint32_t)(mt * 16 * HS_STRIDE) * 4 + ks * 32);
            uint32_t bf[4][2];
            #pragma unroll
            for (int nt = 0; nt < 4; nt++)
                ldsm_x2(bf[nt][0], bf[nt][1],
                        stg + boff + (uint32_t)(nt * 8 * HS_STRIDE) * 4 + ks * 32);
            #pragma unroll
            for (int mt = 0; mt < 4; mt++)
                #pragma unroll
                for (int nt = 0; nt < 4; nt++)
                    mma_f16(acc[mt][nt][0], acc[mt][nt][1], acc[mt][nt][2], acc[mt][nt][3],
                            af[mt][0], af[mt][1], af[mt][2], af[mt][3],
                            bf[nt][0], bf[nt][1]);
        }
    }

    // ---- epilogue ----
    #pragma unroll
    for (int mt = 0; mt < 4; mt++) {
        int gr = bm + wm * 64 + mt * 16 + r4;
        #pragma unroll
        for (int nt = 0; nt < 4; nt++) {
            int gc = bn + wn * 32 + nt * 8 + c4 * 2;
            float b0 = bias[gc], b1 = bias[gc + 1];
            float v[4];
            v[0] = acc[mt][nt][0] + b0;
            v[1] = acc[mt][nt][1] + b1;
            v[2] = acc[mt][nt][2] + b0;
            v[3] = acc[mt][nt][3] + b1;
            #pragma unroll
            for (int u = 0; u < 4; u++) {
                if (EPI == 1) v[u] = 0.5f * v[u] * (1.0f + erff(v[u] * 0.7071067811865476f));
                else if (EPI == 2) v[u] = v[u] > 0.0f ? v[u] : expm1f(v[u]);
                else if (EPI == 3) {
                    if (elu_side) v[u] = v[u] > 0.0f ? v[u] : expm1f(v[u]);
                    else v[u] = 0.5f * v[u] * (1.0f + erff(v[u] * 0.7071067811865476f));
                }
            }
            if (OUTH) {
                __half* Ch = (__half*)C;
                *(uint32_t*)(Ch + (size_t)gr * ldc + gc)       = packh2(v[0], v[1]);
                *(uint32_t*)(Ch + (size_t)(gr + 8) * ldc + gc) = packh2(v[2], v[3]);
            } else {
                float* Cf = (float*)C;
                *(float2*)(Cf + (size_t)gr * ldc + gc)       = make_float2(v[0], v[1]);
                *(float2*)(Cf + (size_t)(gr + 8) * ldc + gc) = make_float2(v[2], v[3]);
            }
        }
    }
}

// ---------------- relative position bias table ----------------
__global__ void pbias_kernel(const float* __restrict__ rel_embed, float* __restrict__ pb)
{
    int d = blockIdx.x * blockDim.x + threadIdx.x;
    if (d >= 2047) return;
    int rel = d - 1023;
    int bucket = (rel > 0) ? 160 : 0;
    int r = rel < 0 ? -rel : rel;
    int val;
    if (r < 80) {
        val = r;
    } else {
        float rf = (float)(r < 1 ? 1 : r);
        float t = logf(rf / 80.0f) / 2.3025851f * 80.0f;
        int large = 80 + (int)t;
        val = large < 159 ? large : 159;
    }
    bucket += val;
    #pragma unroll
    for (int h = 0; h < NHH; h++)
        pb[h * 2048 + d] = rel_embed[bucket * NHH + h];
}

// ---------------- gate kernel v2 ----------------
#define GXS 1088
__global__ void __launch_bounds__(256) gate_kernel(const float* __restrict__ x,
                                                   const float* __restrict__ wgab,
                                                   const float* __restrict__ gc,
                                                   float* __restrict__ gate)
{
    __shared__ float xs[8 * GXS];
    __shared__ float wg[130];
    int tid = threadIdx.x;
    int bs0 = blockIdx.x * 8;
    if (tid < 130) wg[tid] = wgab[tid];
    for (int idx = tid; idx < 8 * 1024; idx += 256) {
        int r = idx >> 10, i = idx & 1023;
        int d = i & 63, h = i >> 6;
        xs[r * GXS + d * 17 + h] = x[(size_t)(bs0 + r) * HH + i];
    }
    __syncthreads();
    int w = tid >> 5, lane = tid & 31;
    int h = lane >> 1, ab = lane & 1;
    float acc = wg[128 + ab];
    const float* xr = xs + w * GXS + h;
    const float* wp = wg + ab * 64;
    #pragma unroll 16
    for (int d = 0; d < 64; d++) acc += xr[d * 17] * wp[d];
    float other = __shfl_xor_sync(0xffffffffu, acc, 1);
    if (ab == 0) {
        float ga = 1.0f / (1.0f + expf(-acc));
        float gb = 1.0f / (1.0f + expf(-other));
        float go = ga * (gb * gc[h] - 1.0f) + 2.0f;
        int bs = bs0 + w;
        int b = bs >> 10, s = bs & 1023;
        gate[(b * NHH + h) * SS + s] = go;
    }
}

// ================= fp16 tensor-core flash attention (2-stage KV pipeline) =================
#define AS 36
#define ATT_WORDS (6*64*AS)
#define ATT_BYTES (ATT_WORDS*4)    // 55296

__global__ void __launch_bounds__(128, 3) attn_tc(const __half* __restrict__ qkv,
                                                  const float* __restrict__ gate,
                                                  const float* __restrict__ pb,
                                                  __half* __restrict__ ctx)
{
    extern __shared__ uint32_t as_[];
    uint32_t* Qs = as_;
    uint32_t* Ps = as_ + 5 * 64 * AS;

    int tid = threadIdx.x, wid = tid >> 5, lane = tid & 31;
    int r4 = lane >> 2, c4 = lane & 3;
    int i0 = blockIdx.x * 64, h = blockIdx.y, b = blockIdx.z;

    const __half* qb = qkv + ((size_t)(b * SS + i0)) * QKVN + h * HDD;
    const __half* kb = qkv + ((size_t)(b * SS)) * QKVN + HH + h * HDD;
    const __half* vb = qkv + ((size_t)(b * SS)) * QKVN + 2 * HH + h * HDD;

    uint32_t ks_sm[2] = { smem_u32(as_ + 1 * 64 * AS), smem_u32(as_ + 2 * 64 * AS) };
    uint32_t vs_sm[2] = { smem_u32(as_ + 3 * 64 * AS), smem_u32(as_ + 4 * 64 * AS) };

    for (int idx = tid; idx < 64 * 8; idx += 128) {
        int r = idx >> 3, cc = idx & 7;
        cp16(ks_sm[0] + (uint32_t)(r * AS + cc * 4) * 4, kb + (size_t)r * QKVN + cc * 8);
        cp16(vs_sm[0] + (uint32_t)(r * AS + cc * 4) * 4, vb + (size_t)r * QKVN + cc * 8);
    }
    CP_COMMIT();

    for (int idx = tid; idx < 64 * 8; idx += 128) {
        int r = idx >> 3, cc = idx & 7;
        *(uint4*)(Qs + r * AS + cc * 4) = *(const uint4*)(qb + (size_t)r * QKVN + cc * 8);
    }
    __syncthreads();

    uint32_t qf[4][4];
    {
        const uint32_t* qp = Qs + (wid * 16 + r4) * AS + c4;
        #pragma unroll
        for (int ks = 0; ks < 4; ks++) {
            qf[ks][0] = qp[ks * 8];
            qf[ks][1] = qp[8 * AS + ks * 8];
            qf[ks][2] = qp[ks * 8 + 4];
            qf[ks][3] = qp[8 * AS + ks * 8 + 4];
        }
    }

    float gate0 = gate[(b * NHH + h) * SS + i0 + wid * 16 + r4];
    float gate1 = gate[(b * NHH + h) * SS + i0 + wid * 16 + r4 + 8];
    const float* pbh = pb + h * 2048 + 1023 - (i0 + wid * 16 + r4);

    float m0 = -INFINITY, m1 = -INFINITY, l0 = 0.0f, l1 = 0.0f;
    float oa[8][4];
    #pragma unroll
    for (int nt = 0; nt < 8; nt++)
        #pragma unroll
        for (int u = 0; u < 4; u++) oa[nt][u] = 0.0f;

    for (int jt = 0; jt < SS / 64; jt++) {
        int st = jt & 1;
        if (jt + 1 < SS / 64) {
            __syncthreads();
            int j1 = (jt + 1) * 64;
            for (int idx = tid; idx < 64 * 8; idx += 128) {
                int r = idx >> 3, cc = idx & 7;
                cp16(ks_sm[st ^ 1] + (uint32_t)(r * AS + cc * 4) * 4,
                     kb + (size_t)(j1 + r) * QKVN + cc * 8);
                cp16(vs_sm[st ^ 1] + (uint32_t)(r * AS + cc * 4) * 4,
                     vb + (size_t)(j1 + r) * QKVN + cc * 8);
            }
            CP_COMMIT();
            CP_WAIT(1);
        } else {
            CP_WAIT(0);
        }
        __syncthreads();

        const uint32_t* Kp = as_ + (1 + st) * 64 * AS;
        uint32_t vls = vs_sm[st] + (uint32_t)(lane & 15) * AS * 4;
        int j0 = jt * 64;

        float sf[8][4];
        #pragma unroll
        for (int nt = 0; nt < 8; nt++)
            #pragma unroll
            for (int u = 0; u < 4; u++) sf[nt][u] = 0.0f;
        #pragma unroll
        for (int ks = 0; ks < 4; ks++) {
            #pragma unroll
            for (int nt = 0; nt < 8; nt++) {
                const uint32_t* p = Kp + (nt * 8 + r4) * AS + ks * 8 + c4;
                mma_f16(sf[nt][0], sf[nt][1], sf[nt][2], sf[nt][3],
                        qf[ks][0], qf[ks][1], qf[ks][2], qf[ks][3],
                        p[0], p[4]);
            }
        }

        #pragma unroll
        for (int nt = 0; nt < 8; nt++) {
            int j = j0 + nt * 8 + 2 * c4;
            float pb0 = pbh[j];
            float pb1 = pbh[j + 1];
            float pb2 = pbh[j - 8];
            float pb3 = pbh[j - 7];
            sf[nt][0] = sf[nt][0] * 0.125f + gate0 * pb0;
            sf[nt][1] = sf[nt][1] * 0.125f + gate0 * pb1;
            sf[nt][2] = sf[nt][2] * 0.125f + gate1 * pb2;
            sf[nt][3] = sf[nt][3] * 0.125f + gate1 * pb3;
        }

        float mx0 = -INFINITY, mx1 = -INFINITY;
        #pragma unroll
        for (int nt = 0; nt < 8; nt++) {
            mx0 = fmaxf(mx0, fmaxf(sf[nt][0], sf[nt][1]));
            mx1 = fmaxf(mx1, fmaxf(sf[nt][2], sf[nt][3]));
        }
        mx0 = fmaxf(mx0, __shfl_xor_sync(0xffffffffu, mx0, 1));
        mx0 = fmaxf(mx0, __shfl_xor_sync(0xffffffffu, mx0, 2));
        mx1 = fmaxf(mx1, __shfl_xor_sync(0xffffffffu, mx1, 1));
        mx1 = fmaxf(mx1, __shfl_xor_sync(0xffffffffu, mx1, 2));
        float mn0 = fmaxf(m0, mx0), mn1 = fmaxf(m1, mx1);
        float a0 = __expf(m0 - mn0), a1 = __expf(m1 - mn1);

        float ls0 = 0.0f, ls1 = 0.0f;
        uint32_t* pr0 = Ps + (wid * 16 + r4) * AS + c4;
        uint32_t* pr1 = pr0 + 8 * AS;
        #pragma unroll
        for (int nt = 0; nt < 8; nt++) {
            float p0 = __expf(sf[nt][0] - mn0);
            float p1 = __expf(sf[nt][1] - mn0);
            float p2 = __expf(sf[nt][2] - mn1);
            float p3 = __expf(sf[nt][3] - mn1);
            ls0 += p0 + p1; ls1 += p2 + p3;
            pr0[nt * 4] = packh2(p0, p1);
            pr1[nt * 4] = packh2(p2, p3);
        }
        ls0 += __shfl_xor_sync(0xffffffffu, ls0, 1);
        ls0 += __shfl_xor_sync(0xffffffffu, ls0, 2);
        ls1 += __shfl_xor_sync(0xffffffffu, ls1, 1);
        ls1 += __shfl_xor_sync(0xffffffffu, ls1, 2);
        l0 = l0 * a0 + ls0;  l1 = l1 * a1 + ls1;
        m0 = mn0;  m1 = mn1;
        #pragma unroll
        for (int nt = 0; nt < 8; nt++) {
            oa[nt][0] *= a0; oa[nt][1] *= a0;
            oa[nt][2] *= a1; oa[nt][3] *= a1;
        }
        __syncwarp();

        const uint32_t* pp = Ps + (wid * 16 + r4) * AS + c4;
        #pragma unroll
        for (int ks = 0; ks < 4; ks++) {
            uint32_t af0 = pp[ks * 8];
            uint32_t af1 = pp[8 * AS + ks * 8];
            uint32_t af2 = pp[ks * 8 + 4];
            uint32_t af3 = pp[8 * AS + ks * 8 + 4];
            uint32_t vrow = vls + (uint32_t)(ks * 16) * AS * 4;
            #pragma unroll
            for (int nt = 0; nt < 8; nt++) {
                uint32_t b0, b1;
                ldsm_x2_trans(b0, b1, vrow + nt * 16);
                mma_f16(oa[nt][0], oa[nt][1], oa[nt][2], oa[nt][3],
                        af0, af1, af2, af3, b0, b1);
            }
        }
    }

    float inv0 = 1.0f / l0, inv1 = 1.0f / l1;
    __half* cb0 = ctx + ((size_t)(b * SS + i0 + wid * 16 + r4)) * HH + h * HDD;
    __half* cb1 = cb0 + 8 * HH;
    #pragma unroll
    for (int nt = 0; nt < 8; nt++) {
        *(uint32_t*)(cb0 + nt * 8 + 2 * c4) = packh2(oa[nt][0] * inv0, oa[nt][1] * inv0);
        *(uint32_t*)(cb1 + nt * 8 + 2 * c4) = packh2(oa[nt][2] * inv1, oa[nt][3] * inv1);
    }
}

// ---------------- residual-add + LayerNorm (+ optional half copy) ----------------
__global__ void ln_kernel(const float* __restrict__ A, const float* __restrict__ B,
                          const float* __restrict__ g, const float* __restrict__ bt,
                          float* __restrict__ out, __half* __restrict__ out2)
{
    __shared__ float sm[8];
    int row = blockIdx.x;
    int t = threadIdx.x;
    size_t base = (size_t)row * HH;
    float vals[4];
    #pragma unroll
    for (int u = 0; u < 4; u++) {
        int i = t + u*256;
        vals[u] = A[base + i] + B[base + i];
    }
    float sum = vals[0] + vals[1] + vals[2] + vals[3];
    #pragma unroll
    for (int off = 16; off >= 1; off >>= 1) sum += __shfl_xor_sync(0xffffffffu, sum, off);
    if ((t & 31) == 0) sm[t >> 5] = sum;
    __syncthreads();
    float tot = 0.0f;
    #pragma unroll
    for (int w = 0; w < 8; w++) tot += sm[w];
    float mean = tot * (1.0f / HH);
    __syncthreads();
    float vs = 0.0f;
    #pragma unroll
    for (int u = 0; u < 4; u++) { float d = vals[u] - mean; vs += d * d; }
    #pragma unroll
    for (int off = 16; off >= 1; off >>= 1) vs += __shfl_xor_sync(0xffffffffu, vs, off);
    if ((t & 31) == 0) sm[t >> 5] = vs;
    __syncthreads();
    float vtot = 0.0f;
    #pragma unroll
    for (int w = 0; w < 8; w++) vtot += sm[w];
    float rstd = rsqrtf(vtot * (1.0f / HH) + EPSF);
    #pragma unroll
    for (int u = 0; u < 4; u++) {
        int i = t + u*256;
        float r = (vals[u] - mean) * rstd * g[i] + bt[i];
        out[base + i] = r;
        if (out2) out2[base + i] = __float2half_rn(r);
    }
}

// ---------------- launch ----------------
extern "C" void kernel_launch(void* const* d_in, const int* in_sizes, int n_in,
                              void* d_out, int out_size)
{
    const float* x   = (const float*)d_in[0];
    const float* Wq  = (const float*)d_in[1];
    const float* bq  = (const float*)d_in[2];
    const float* Wk  = (const float*)d_in[3];
    const float* bk  = (const float*)d_in[4];
    const float* Wv  = (const float*)d_in[5];
    const float* bv  = (const float*)d_in[6];
    const float* Wo  = (const float*)d_in[7];
    const float* bo  = (const float*)d_in[8];
    const float* Wg  = (const float*)d_in[9];
    const float* bg  = (const float*)d_in[10];
    const float* gru = (const float*)d_in[11];
    const float* rel = (const float*)d_in[12];
    const float* l1g = (const float*)d_in[13];
    const float* l1b = (const float*)d_in[14];
    const float* W1  = (const float*)d_in[15];
    const float* b1  = (const float*)d_in[16];
    const float* W2  = (const float*)d_in[17];
    const float* b2  = (const float*)d_in[18];
    const float* l2g = (const float*)d_in[19];
    const float* l2b = (const float*)d_in[20];
    const float* Wad = (const float*)d_in[21];
    const float* bad = (const float*)d_in[22];
    const float* Wau = (const float*)d_in[23];
    const float* bau = (const float*)d_in[24];
    float* out = (float*)d_out;

    __half *pqkv, *pctx, *phr, *pff1, *pxr, *pwqkv, *pwo, *pw1c, *pw2c;
    float *patt, *ph, *pff2, *pgate, *ppb, *pbqkv, *pb2c, *pb1c, *pwgab;
    cudaGetSymbolAddress((void**)&pqkv, g_qkv);
    cudaGetSymbolAddress((void**)&pctx, g_ctx);
    cudaGetSymbolAddress((void**)&patt, g_att);
    cudaGetSymbolAddress((void**)&ph,   g_h);
    cudaGetSymbolAddress((void**)&phr,  g_hr);
    cudaGetSymbolAddress((void**)&pff1, g_ff1);
    cudaGetSymbolAddress((void**)&pff2, g_ff2);
    cudaGetSymbolAddress((void**)&pgate, g_gate);
    cudaGetSymbolAddress((void**)&ppb,  g_pb);
    cudaGetSymbolAddress((void**)&pxr,  g_xr);
    cudaGetSymbolAddress((void**)&pwqkv, g_wqkv);
    cudaGetSymbolAddress((void**)&pwo,  g_wo);
    cudaGetSymbolAddress((void**)&pw1c, g_w1c);
    cudaGetSymbolAddress((void**)&pw2c, g_w2c);
    cudaGetSymbolAddress((void**)&pbqkv, g_bqkv);
    cudaGetSymbolAddress((void**)&pb2c, g_b2c);
    cudaGetSymbolAddress((void**)&pb1c, g_b1c);
    cudaGetSymbolAddress((void**)&pwgab, g_wgab);

    cudaFuncSetAttribute(gemm_h<0,0>, cudaFuncAttributeMaxDynamicSharedMemorySize, HS_BYTES);
    cudaFuncSetAttribute(gemm_h<0,1>, cudaFuncAttributeMaxDynamicSharedMemorySize, HS_BYTES);
    cudaFuncSetAttribute(gemm_h<3,1>, cudaFuncAttributeMaxDynamicSharedMemorySize, HS_BYTES);
    cudaFuncSetAttribute(attn_tc, cudaFuncAttributeMaxDynamicSharedMemorySize, ATT_BYTES);

    // launches 1-3
    pack_weights<<<(PW_TOT + 255)/256, 256>>>(Wq, Wk, Wv, Wo, W1, Wad, W2, Wau,
                                              pwqkv, pwo, pw1c, pw2c);
    pack_h<<<(MM*HH)/2048, 256>>>(x, pxr, MM*HH);
    bias_prep<<<(4*HH + FAK + 130 + 255)/256, 256>>>(bq, bk, bv, b2, bau, b1, bad,
                                                     Wg, bg, pbqkv, pb2c, pb1c, pwgab);
    // 4) fused QKV projection  (ncu capture target)
    gemm_h<0,1><<<dim3(QKVN/128, MM/128), 256, HS_BYTES>>>(pxr, pwqkv, pbqkv, pqkv, MM, QKVN, HH, QKVN);
    // 5-6) pos bias + gates
    pbias_kernel<<<(2047 + 127) / 128, 128>>>(rel, ppb);
    gate_kernel<<<MM/8, 256>>>(x, pwgab, gru, pgate);
    // 7) attention
    attn_tc<<<dim3(SS/64, NHH, BB), 128, ATT_BYTES>>>(pqkv, pgate, ppb, pctx);
    // 8) output projection (float out)
    gemm_h<0,0><<<dim3(HH/128, MM/128), 256, HS_BYTES>>>(pctx, pwo, bo, patt, MM, HH, HH, HH);
    // 9) residual + LN1
    ln_kernel<<<MM, 256>>>(x, patt, l1g, l1b, ph, phr);
    // 10) fused FFN-up(gelu) + adapter-down(elu)
    gemm_h<3,1><<<dim3(FAK/128, MM/128), 256, HS_BYTES>>>(phr, pw1c, pb1c, pff1, MM, FAK, HH, FAK);
    // 11) fused FFN-down + adapter-up
    gemm_h<0,0><<<dim3(HH/128, MM/128), 256, HS_BYTES>>>(pff1, pw2c, pb2c, pff2, MM, HH, FAK, HH);
    // 12) h + (ff+adapt), LN2 -> out
    ln_kernel<<<MM, 256>>>(ph, pff2, l2g, l2b, out, nullptr);
}

// round 15
// speedup vs baseline: 1.3776x; 1.0188x over previous
#include <cuda_runtime.h>
#include <cuda_fp16.h>
#include <math.h>
#include <stdint.h>

// ---------------- problem constants ----------------
#define BB   4
#define SS   1024
#define HH   1024
#define NHH  16
#define HDD  64
#define FFF  4096
#define ADD  256
#define MM   (BB*SS)          // 4096 rows
#define EPSF 1e-5f
#define QKVN 3072
#define FAK  (FFF+ADD)        // 4352

// ---------------- scratch ----------------
__device__ __half g_qkv [(size_t)MM*QKVN];
__device__ __half g_ctx [MM*HH];
__device__ float  g_att [MM*HH];
__device__ float  g_h   [MM*HH];
__device__ __half g_hr  [MM*HH];
__device__ __half g_ff1 [(size_t)MM*FAK];
__device__ float  g_ff2 [MM*HH];
__device__ float  g_gate[BB*NHH*SS];
__device__ float  g_pb  [NHH*2048];
// fp16 operand copies
__device__ __half g_xr  [MM*HH];
__device__ __half g_wqkv[QKVN*HH];
__device__ __half g_wo  [HH*HH];
__device__ __half g_w1c [(size_t)FAK*HH];
__device__ __half g_w2c [(size_t)HH*FAK];
__device__ float  g_bqkv[QKVN];
__device__ float  g_b2c [HH];
__device__ float  g_b1c [FAK];
__device__ float  g_wgab[130];

// ---------------- helpers ----------------
__device__ __forceinline__ uint32_t smem_u32(const void* p) {
    uint32_t a;
    asm("{ .reg .u64 t; cvta.to.shared.u64 t, %1; cvt.u32.u64 %0, t; }" : "=r"(a) : "l"(p));
    return a;
}
__device__ __forceinline__ void cp16(uint32_t s, const void* g) {
    asm volatile("cp.async.cg.shared.global [%0], [%1], 16;" :: "r"(s), "l"(g));
}
#define CP_COMMIT() asm volatile("cp.async.commit_group;")
#define CP_WAIT(N)  asm volatile("cp.async.wait_group %0;" :: "n"(N))

__device__ __forceinline__ void mma_f16(float& c0, float& c1, float& c2, float& c3,
                                        uint32_t a0, uint32_t a1, uint32_t a2, uint32_t a3,
                                        uint32_t b0, uint32_t b1) {
    asm volatile(
        "mma.sync.aligned.m16n8k16.row.col.f32.f16.f16.f32 "
        "{%0,%1,%2,%3}, {%4,%5,%6,%7}, {%8,%9}, {%0,%1,%2,%3};\n"
        : "+f"(c0), "+f"(c1), "+f"(c2), "+f"(c3)
        : "r"(a0), "r"(a1), "r"(a2), "r"(a3), "r"(b0), "r"(b1));
}
__device__ __forceinline__ void ldsm_x4(uint32_t& r0, uint32_t& r1, uint32_t& r2, uint32_t& r3,
                                        uint32_t addr) {
    asm volatile("ldmatrix.sync.aligned.m8n8.x4.shared.b16 {%0,%1,%2,%3}, [%4];"
                 : "=r"(r0), "=r"(r1), "=r"(r2), "=r"(r3) : "r"(addr));
}
__device__ __forceinline__ void ldsm_x2(uint32_t& r0, uint32_t& r1, uint32_t addr) {
    asm volatile("ldmatrix.sync.aligned.m8n8.x2.shared.b16 {%0,%1}, [%2];"
                 : "=r"(r0), "=r"(r1) : "r"(addr));
}
__device__ __forceinline__ void ldsm_x2_trans(uint32_t& b0, uint32_t& b1, uint32_t addr) {
    asm volatile("ldmatrix.sync.aligned.m8n8.x2.trans.shared.b16 {%0,%1}, [%2];"
                 : "=r"(b0), "=r"(b1) : "r"(addr));
}
__device__ __forceinline__ uint32_t packh2(float a, float b) {
    __half2 h = __floats2half2_rn(a, b);
    return *(uint32_t*)&h;
}

// ---------------- f32 -> f16 packers ----------------
__device__ __forceinline__ void pack8(const float* in, __half* out) {
    float4 a = *(const float4*)(in);
    float4 b = *(const float4*)(in + 4);
    uint4 o;
    o.x = packh2(a.x, a.y); o.y = packh2(a.z, a.w);
    o.z = packh2(b.x, b.y); o.w = packh2(b.z, b.w);
    *(uint4*)(out) = o;
}
__global__ void pack_h(const float* __restrict__ in, __half* __restrict__ out, int n)
{
    int i = (blockIdx.x * 256 + threadIdx.x) * 8;
    if (i < n) pack8(in + i, out + i);
}
// fused pack of ALL weights — segment END boundaries in 8-elem units
#define PW_Q   131072
#define PW_K   262144
#define PW_V   393216
#define PW_O   524288
#define PW_1   1048576
#define PW_AD  1081344
#define PW_2   1605632
#define PW_TOT 1638400
__global__ void pack_weights(const float* __restrict__ Wq, const float* __restrict__ Wk,
                             const float* __restrict__ Wv, const float* __restrict__ Wo,
                             const float* __restrict__ W1, const float* __restrict__ Wad,
                             const float* __restrict__ W2, const float* __restrict__ Wau,
                             __half* __restrict__ wqkv, __half* __restrict__ wo,
                             __half* __restrict__ w1c, __half* __restrict__ w2c)
{
    int u = blockIdx.x * 256 + threadIdx.x;
    if (u >= PW_TOT) return;
    if (u < PW_Q)       { int i = u*8;           pack8(Wq + i,  wqkv + i); }
    else if (u < PW_K)  { int i = (u-PW_Q)*8;    pack8(Wk + i,  wqkv + HH*HH + i); }
    else if (u < PW_V)  { int i = (u-PW_K)*8;    pack8(Wv + i,  wqkv + 2*HH*HH + i); }
    else if (u < PW_O)  { int i = (u-PW_V)*8;    pack8(Wo + i,  wo + i); }
    else if (u < PW_1)  { int i = (u-PW_O)*8;    pack8(W1 + i,  w1c + i); }
    else if (u < PW_AD) { int i = (u-PW_1)*8;    pack8(Wad + i, w1c + (size_t)FFF*HH + i); }
    else if (u < PW_2)  { int i = (u-PW_AD)*8;   int r = i / FFF, c = i - r*FFF;
                          pack8(W2 + i,  w2c + (size_t)r*FAK + c); }
    else                { int i = (u-PW_2)*8;    int r = i / ADD, c = i - r*ADD;
                          pack8(Wau + i, w2c + (size_t)r*FAK + FFF + c); }
}
// fused bias prep
__global__ void bias_prep(const float* __restrict__ bq, const float* __restrict__ bk,
                          const float* __restrict__ bv, const float* __restrict__ b2,
                          const float* __restrict__ bau, const float* __restrict__ b1,
                          const float* __restrict__ bad,
                          const float* __restrict__ Wg, const float* __restrict__ bg,
                          float* __restrict__ bqkv, float* __restrict__ b2c,
                          float* __restrict__ b1c, float* __restrict__ wgab)
{
    int i = blockIdx.x * 256 + threadIdx.x;
    if (i < HH)                 bqkv[i] = bq[i];
    else if (i < 2*HH)          bqkv[i] = bk[i - HH];
    else if (i < 3*HH)          bqkv[i] = bv[i - 2*HH];
    else if (i < 4*HH)          { int j = i - 3*HH; b2c[j] = b2[j] + bau[j]; }
    else if (i < 4*HH + FAK)    { int j = i - 4*HH;
                                  b1c[j] = (j < FFF) ? b1[j] : bad[j - FFF]; }
    else if (i < 4*HH+FAK+64)   { int d = i - 4*HH - FAK;
                                  wgab[d] = Wg[d] + Wg[64+d] + Wg[128+d] + Wg[192+d]; }
    else if (i < 4*HH+FAK+128)  { int d = i - 4*HH - FAK - 64;
                                  wgab[64+d] = Wg[256+d] + Wg[320+d] + Wg[384+d] + Wg[448+d]; }
    else if (i == 4*HH+FAK+128) wgab[128] = bg[0] + bg[1] + bg[2] + bg[3];
    else if (i == 4*HH+FAK+129) wgab[129] = bg[4] + bg[5] + bg[6] + bg[7];
}

// ================= fp16 mma.sync GEMM (128x128, 8 warps, ldmatrix, 4-stage) =================
#define HS_STRIDE 20
#define HS_AWORDS (128*HS_STRIDE)
#define HS_STAGEW (2*HS_AWORDS)
#define HS_BYTES  (4*HS_STAGEW*4)   // 81920

template<int EPI, int OUTH>   // EPI: 0=none,1=gelu,2=elu,3=mixed
__global__ void __launch_bounds__(256, 2) gemm_h(const __half* __restrict__ A,
                                                 const __half* __restrict__ W,
                                                 const float* __restrict__ bias,
                                                 void* __restrict__ C,
                                                 int M, int N, int K, int ldc)
{
    extern __shared__ uint32_t sm[];
    int tid  = threadIdx.x;
    int wid  = tid >> 5, lane = tid & 31;
    int wm   = wid >> 2;          // 0..1
    int wn   = wid & 3;           // 0..3
    int bm = blockIdx.y * 128, bn = blockIdx.x * 128;
    int r4 = lane >> 2;
    int c4 = lane & 3;
    bool elu_side = (EPI == 3) && (bn >= FFF);

    float acc[4][4][4];
    #pragma unroll
    for (int mt = 0; mt < 4; mt++)
        #pragma unroll
        for (int nt = 0; nt < 4; nt++)
            #pragma unroll
            for (int u = 0; u < 4; u++) acc[mt][nt][u] = 0.0f;

    int lrow = tid >> 2;            // 0..63
    int lcc  = tid & 3;             // 16B chunk
    const __half* aptr = A + (size_t)(bm + lrow) * K + lcc * 8;
    const __half* wptr = W + (size_t)(bn + lrow) * K + lcc * 8;
    uint32_t sb = smem_u32(sm);
    uint32_t sa_base = sb + (uint32_t)(lrow * HS_STRIDE + lcc * 4) * 4;

    uint32_t aoff = (uint32_t)((wm * 64 + (lane & 15)) * HS_STRIDE) * 4 + (lane >> 4) * 16;
    uint32_t boff = (uint32_t)(HS_AWORDS * 4)
                  + (uint32_t)((wn * 32 + (lane & 7)) * HS_STRIDE) * 4 + ((lane >> 3) & 1) * 16;

    int T = K >> 5;

    // prologue: tiles 0,1,2 -> stages 0,1,2
    #pragma unroll
    for (int t0 = 0; t0 < 3; t0++) {
        const __half* ap = aptr + t0 * 32;
        const __half* wp = wptr + t0 * 32;
        uint32_t so = sa_base + (uint32_t)(t0 * HS_STAGEW) * 4;
        #pragma unroll
        for (int i = 0; i < 2; i++) {
            cp16(so + (uint32_t)(i * 64 * HS_STRIDE) * 4, ap + (size_t)(i * 64) * K);
            cp16(so + (uint32_t)(HS_AWORDS + i * 64 * HS_STRIDE) * 4, wp + (size_t)(i * 64) * K);
        }
        CP_COMMIT();
    }

    for (int k0 = 0; k0 < T; k0++) {
        int stage = k0 & 3;
        if (k0 + 2 < T)      { CP_WAIT(2); }
        else if (k0 + 1 < T) { CP_WAIT(1); }
        else                 { CP_WAIT(0); }
        __syncthreads();
        if (k0 + 3 < T) {
            int ns = (k0 + 3) & 3;
            const __half* ap = aptr + (k0 + 3) * 32;
            const __half* wp = wptr + (k0 + 3) * 32;
            uint32_t so = sa_base + (uint32_t)(ns * HS_STAGEW) * 4;
            #pragma unroll
            for (int i = 0; i < 2; i++) {
                cp16(so + (uint32_t)(i * 64 * HS_STRIDE) * 4, ap + (size_t)(i * 64) * K);
                cp16(so + (uint32_t)(HS_AWORDS + i * 64 * HS_STRIDE) * 4, wp + (size_t)(i * 64) * K);
            }
            CP_COMMIT();
        }
        uint32_t stg = sb + (uint32_t)(stage * HS_STAGEW) * 4;
        #pragma unroll
        for (int ks = 0; ks < 2; ks++) {
            uint32_t af[4][4];
            #pragma unroll
            for (int mt = 0; mt < 4; mt++)
                ldsm_x4(af[mt][0], af[mt][1], af[mt][2], af[mt][3],
                        stg + aoff + (uint32_t)(mt * 16 * HS_STRIDE) * 4 + ks * 32);
            uint32_t bf[4][2];
            #pragma unroll
            for (int nt = 0; nt < 4; nt++)
                ldsm_x2(bf[nt][0], bf[nt][1],
                        stg + boff + (uint32_t)(nt * 8 * HS_STRIDE) * 4 + ks * 32);
            #pragma unroll
            for (int mt = 0; mt < 4; mt++)
                #pragma unroll
                for (int nt = 0; nt < 4; nt++)
                    mma_f16(acc[mt][nt][0], acc[mt][nt][1], acc[mt][nt][2], acc[mt][nt][3],
                            af[mt][0], af[mt][1], af[mt][2], af[mt][3],
                            bf[nt][0], bf[nt][1]);
        }
    }

    // ---- epilogue ----
    #pragma unroll
    for (int mt = 0; mt < 4; mt++) {
        int gr = bm + wm * 64 + mt * 16 + r4;
        #pragma unroll
        for (int nt = 0; nt < 4; nt++) {
            int gc = bn + wn * 32 + nt * 8 + c4 * 2;
            float b0 = bias[gc], b1 = bias[gc + 1];
            float v[4];
            v[0] = acc[mt][nt][0] + b0;
            v[1] = acc[mt][nt][1] + b1;
            v[2] = acc[mt][nt][2] + b0;
            v[3] = acc[mt][nt][3] + b1;
            #pragma unroll
            for (int u = 0; u < 4; u++) {
                if (EPI == 1) v[u] = 0.5f * v[u] * (1.0f + erff(v[u] * 0.7071067811865476f));
                else if (EPI == 2) v[u] = v[u] > 0.0f ? v[u] : expm1f(v[u]);
                else if (EPI == 3) {
                    if (elu_side) v[u] = v[u] > 0.0f ? v[u] : expm1f(v[u]);
                    else v[u] = 0.5f * v[u] * (1.0f + erff(v[u] * 0.7071067811865476f));
                }
            }
            if (OUTH) {
                __half* Ch = (__half*)C;
                *(uint32_t*)(Ch + (size_t)gr * ldc + gc)       = packh2(v[0], v[1]);
                *(uint32_t*)(Ch + (size_t)(gr + 8) * ldc + gc) = packh2(v[2], v[3]);
            } else {
                float* Cf = (float*)C;
                *(float2*)(Cf + (size_t)gr * ldc + gc)       = make_float2(v[0], v[1]);
                *(float2*)(Cf + (size_t)(gr + 8) * ldc + gc) = make_float2(v[2], v[3]);
            }
        }
    }
}

// ---------------- relative position bias table ----------------
__global__ void pbias_kernel(const float* __restrict__ rel_embed, float* __restrict__ pb)
{
    int d = blockIdx.x * blockDim.x + threadIdx.x;
    if (d >= 2047) return;
    int rel = d - 1023;
    int bucket = (rel > 0) ? 160 : 0;
    int r = rel < 0 ? -rel : rel;
    int val;
    if (r < 80) {
        val = r;
    } else {
        float rf = (float)(r < 1 ? 1 : r);
        float t = logf(rf / 80.0f) / 2.3025851f * 80.0f;
        int large = 80 + (int)t;
        val = large < 159 ? large : 159;
    }
    bucket += val;
    #pragma unroll
    for (int h = 0; h < NHH; h++)
        pb[h * 2048 + d] = rel_embed[bucket * NHH + h];
}

// ---------------- gate kernel v2 ----------------
#define GXS 1088
__global__ void __launch_bounds__(256) gate_kernel(const float* __restrict__ x,
                                                   const float* __restrict__ wgab,
                                                   const float* __restrict__ gc,
                                                   float* __restrict__ gate)
{
    __shared__ float xs[8 * GXS];
    __shared__ float wg[130];
    int tid = threadIdx.x;
    int bs0 = blockIdx.x * 8;
    if (tid < 130) wg[tid] = wgab[tid];
    for (int idx = tid; idx < 8 * 1024; idx += 256) {
        int r = idx >> 10, i = idx & 1023;
        int d = i & 63, h = i >> 6;
        xs[r * GXS + d * 17 + h] = x[(size_t)(bs0 + r) * HH + i];
    }
    __syncthreads();
    int w = tid >> 5, lane = tid & 31;
    int h = lane >> 1, ab = lane & 1;
    float acc = wg[128 + ab];
    const float* xr = xs + w * GXS + h;
    const float* wp = wg + ab * 64;
    #pragma unroll 16
    for (int d = 0; d < 64; d++) acc += xr[d * 17] * wp[d];
    float other = __shfl_xor_sync(0xffffffffu, acc, 1);
    if (ab == 0) {
        float ga = 1.0f / (1.0f + expf(-acc));
        float gb = 1.0f / (1.0f + expf(-other));
        float go = ga * (gb * gc[h] - 1.0f) + 2.0f;
        int bs = bs0 + w;
        int b = bs >> 10, s = bs & 1023;
        gate[(b * NHH + h) * SS + s] = go;
    }
}

// ===== fp16 flash attention: register-resident P, 2-stage KV pipeline =====
#define AS 36
// Qs | Ks[2] | Vs[2]  : 5 buffers of 64*AS words (no Ps)
#define ATT_WORDS (5*64*AS)
#define ATT_BYTES (ATT_WORDS*4)    // 46080

__global__ void __launch_bounds__(128, 4) attn_tc(const __half* __restrict__ qkv,
                                                  const float* __restrict__ gate,
                                                  const float* __restrict__ pb,
                                                  __half* __restrict__ ctx)
{
    extern __shared__ uint32_t as_[];
    uint32_t* Qs = as_;

    int tid = threadIdx.x, wid = tid >> 5, lane = tid & 31;
    int r4 = lane >> 2, c4 = lane & 3;
    int i0 = blockIdx.x * 64, h = blockIdx.y, b = blockIdx.z;

    const __half* qb = qkv + ((size_t)(b * SS + i0)) * QKVN + h * HDD;
    const __half* kb = qkv + ((size_t)(b * SS)) * QKVN + HH + h * HDD;
    const __half* vb = qkv + ((size_t)(b * SS)) * QKVN + 2 * HH + h * HDD;

    uint32_t ks_sm[2] = { smem_u32(as_ + 1 * 64 * AS), smem_u32(as_ + 2 * 64 * AS) };
    uint32_t vs_sm[2] = { smem_u32(as_ + 3 * 64 * AS), smem_u32(as_ + 4 * 64 * AS) };

    // issue KV tile 0 first, overlapping with Q staging
    for (int idx = tid; idx < 64 * 8; idx += 128) {
        int r = idx >> 3, cc = idx & 7;
        cp16(ks_sm[0] + (uint32_t)(r * AS + cc * 4) * 4, kb + (size_t)r * QKVN + cc * 8);
        cp16(vs_sm[0] + (uint32_t)(r * AS + cc * 4) * 4, vb + (size_t)r * QKVN + cc * 8);
    }
    CP_COMMIT();

    for (int idx = tid; idx < 64 * 8; idx += 128) {
        int r = idx >> 3, cc = idx & 7;
        *(uint4*)(Qs + r * AS + cc * 4) = *(const uint4*)(qb + (size_t)r * QKVN + cc * 8);
    }
    __syncthreads();

    uint32_t qf[4][4];
    {
        const uint32_t* qp = Qs + (wid * 16 + r4) * AS + c4;
        #pragma unroll
        for (int ks = 0; ks < 4; ks++) {
            qf[ks][0] = qp[ks * 8];
            qf[ks][1] = qp[8 * AS + ks * 8];
            qf[ks][2] = qp[ks * 8 + 4];
            qf[ks][3] = qp[8 * AS + ks * 8 + 4];
        }
    }

    float gate0 = gate[(b * NHH + h) * SS + i0 + wid * 16 + r4];
    float gate1 = gate[(b * NHH + h) * SS + i0 + wid * 16 + r4 + 8];
    const float* pbh = pb + h * 2048 + 1023 - (i0 + wid * 16 + r4);

    float m0 = -INFINITY, m1 = -INFINITY, l0 = 0.0f, l1 = 0.0f;
    float oa[8][4];
    #pragma unroll
    for (int nt = 0; nt < 8; nt++)
        #pragma unroll
        for (int u = 0; u < 4; u++) oa[nt][u] = 0.0f;

    for (int jt = 0; jt < SS / 64; jt++) {
        int st = jt & 1;
        if (jt + 1 < SS / 64) {
            __syncthreads();   // all warps done reading stage st^1
            int j1 = (jt + 1) * 64;
            for (int idx = tid; idx < 64 * 8; idx += 128) {
                int r = idx >> 3, cc = idx & 7;
                cp16(ks_sm[st ^ 1] + (uint32_t)(r * AS + cc * 4) * 4,
                     kb + (size_t)(j1 + r) * QKVN + cc * 8);
                cp16(vs_sm[st ^ 1] + (uint32_t)(r * AS + cc * 4) * 4,
                     vb + (size_t)(j1 + r) * QKVN + cc * 8);
            }
            CP_COMMIT();
            CP_WAIT(1);
        } else {
            CP_WAIT(0);
        }
        __syncthreads();       // tile jt visible

        const uint32_t* Kp = as_ + (1 + st) * 64 * AS;
        uint32_t vls = vs_sm[st] + (uint32_t)(lane & 15) * AS * 4;
        int j0 = jt * 64;

        // ---- S = Q K^T ----
        float sf[8][4];
        #pragma unroll
        for (int nt = 0; nt < 8; nt++)
            #pragma unroll
            for (int u = 0; u < 4; u++) sf[nt][u] = 0.0f;
        #pragma unroll
        for (int ks = 0; ks < 4; ks++) {
            #pragma unroll
            for (int nt = 0; nt < 8; nt++) {
                const uint32_t* p = Kp + (nt * 8 + r4) * AS + ks * 8 + c4;
                mma_f16(sf[nt][0], sf[nt][1], sf[nt][2], sf[nt][3],
                        qf[ks][0], qf[ks][1], qf[ks][2], qf[ks][3],
                        p[0], p[4]);
            }
        }

        // ---- scale + gated relative bias ----
        #pragma unroll
        for (int nt = 0; nt < 8; nt++) {
            int j = j0 + nt * 8 + 2 * c4;
            float pb0 = pbh[j];
            float pb1 = pbh[j + 1];
            float pb2 = pbh[j - 8];
            float pb3 = pbh[j - 7];
            sf[nt][0] = sf[nt][0] * 0.125f + gate0 * pb0;
            sf[nt][1] = sf[nt][1] * 0.125f + gate0 * pb1;
            sf[nt][2] = sf[nt][2] * 0.125f + gate1 * pb2;
            sf[nt][3] = sf[nt][3] * 0.125f + gate1 * pb3;
        }

        // ---- online softmax ----
        float mx0 = -INFINITY, mx1 = -INFINITY;
        #pragma unroll
        for (int nt = 0; nt < 8; nt++) {
            mx0 = fmaxf(mx0, fmaxf(sf[nt][0], sf[nt][1]));
            mx1 = fmaxf(mx1, fmaxf(sf[nt][2], sf[nt][3]));
        }
        mx0 = fmaxf(mx0, __shfl_xor_sync(0xffffffffu, mx0, 1));
        mx0 = fmaxf(mx0, __shfl_xor_sync(0xffffffffu, mx0, 2));
        mx1 = fmaxf(mx1, __shfl_xor_sync(0xffffffffu, mx1, 1));
        mx1 = fmaxf(mx1, __shfl_xor_sync(0xffffffffu, mx1, 2));
        float mn0 = fmaxf(m0, mx0), mn1 = fmaxf(m1, mx1);
        float a0 = __expf(m0 - mn0), a1 = __expf(m1 - mn1);

        // exp + pack P fragments directly (no smem round-trip)
        uint32_t pa[4][4];
        float ls0 = 0.0f, ls1 = 0.0f;
        #pragma unroll
        for (int nt = 0; nt < 8; nt++) {
            float p0 = __expf(sf[nt][0] - mn0);
            float p1 = __expf(sf[nt][1] - mn0);
            float p2 = __expf(sf[nt][2] - mn1);
            float p3 = __expf(sf[nt][3] - mn1);
            ls0 += p0 + p1; ls1 += p2 + p3;
            int ks = nt >> 1;
            if ((nt & 1) == 0) {
                pa[ks][0] = packh2(p0, p1);
                pa[ks][1] = packh2(p2, p3);
            } else {
                pa[ks][2] = packh2(p0, p1);
                pa[ks][3] = packh2(p2, p3);
            }
        }
        ls0 += __shfl_xor_sync(0xffffffffu, ls0, 1);
        ls0 += __shfl_xor_sync(0xffffffffu, ls0, 2);
        ls1 += __shfl_xor_sync(0xffffffffu, ls1, 1);
        ls1 += __shfl_xor_sync(0xffffffffu, ls1, 2);
        l0 = l0 * a0 + ls0;  l1 = l1 * a1 + ls1;
        m0 = mn0;  m1 = mn1;
        #pragma unroll
        for (int nt = 0; nt < 8; nt++) {
            oa[nt][0] *= a0; oa[nt][1] *= a0;
            oa[nt][2] *= a1; oa[nt][3] *= a1;
        }

        // ---- O += P V  (P from registers, V transposed via ldmatrix.trans) ----
        #pragma unroll
        for (int ks = 0; ks < 4; ks++) {
            uint32_t vrow = vls + (uint32_t)(ks * 16) * AS * 4;
            #pragma unroll
            for (int nt = 0; nt < 8; nt++) {
                uint32_t b0, b1;
                ldsm_x2_trans(b0, b1, vrow + nt * 16);
                mma_f16(oa[nt][0], oa[nt][1], oa[nt][2], oa[nt][3],
                        pa[ks][0], pa[ks][1], pa[ks][2], pa[ks][3], b0, b1);
            }
        }
    }

    float inv0 = 1.0f / l0, inv1 = 1.0f / l1;
    __half* cb0 = ctx + ((size_t)(b * SS + i0 + wid * 16 + r4)) * HH + h * HDD;
    __half* cb1 = cb0 + 8 * HH;
    #pragma unroll
    for (int nt = 0; nt < 8; nt++) {
        *(uint32_t*)(cb0 + nt * 8 + 2 * c4) = packh2(oa[nt][0] * inv0, oa[nt][1] * inv0);
        *(uint32_t*)(cb1 + nt * 8 + 2 * c4) = packh2(oa[nt][2] * inv1, oa[nt][3] * inv1);
    }
}

// ---------------- residual-add + LayerNorm (+ optional half copy) ----------------
__global__ void ln_kernel(const float* __restrict__ A, const float* __restrict__ B,
                          const float* __restrict__ g, const float* __restrict__ bt,
                          float* __restrict__ out, __half* __restrict__ out2)
{
    __shared__ float sm[8];
    int row = blockIdx.x;
    int t = threadIdx.x;
    size_t base = (size_t)row * HH;
    float vals[4];
    #pragma unroll
    for (int u = 0; u < 4; u++) {
        int i = t + u*256;
        vals[u] = A[base + i] + B[base + i];
    }
    float sum = vals[0] + vals[1] + vals[2] + vals[3];
    #pragma unroll
    for (int off = 16; off >= 1; off >>= 1) sum += __shfl_xor_sync(0xffffffffu, sum, off);
    if ((t & 31) == 0) sm[t >> 5] = sum;
    __syncthreads();
    float tot = 0.0f;
    #pragma unroll
    for (int w = 0; w < 8; w++) tot += sm[w];
    float mean = tot * (1.0f / HH);
    __syncthreads();
    float vs = 0.0f;
    #pragma unroll
    for (int u = 0; u < 4; u++) { float d = vals[u] - mean; vs += d * d; }
    #pragma unroll
    for (int off = 16; off >= 1; off >>= 1) vs += __shfl_xor_sync(0xffffffffu, vs, off);
    if ((t & 31) == 0) sm[t >> 5] = vs;
    __syncthreads();
    float vtot = 0.0f;
    #pragma unroll
    for (int w = 0; w < 8; w++) vtot += sm[w];
    float rstd = rsqrtf(vtot * (1.0f / HH) + EPSF);
    #pragma unroll
    for (int u = 0; u < 4; u++) {
        int i = t + u*256;
        float r = (vals[u] - mean) * rstd * g[i] + bt[i];
        out[base + i] = r;
        if (out2) out2[base + i] = __float2half_rn(r);
    }
}

// ---------------- launch ----------------
extern "C" void kernel_launch(void* const* d_in, const int* in_sizes, int n_in,
                              void* d_out, int out_size)
{
    const float* x   = (const float*)d_in[0];
    const float* Wq  = (const float*)d_in[1];
    const float* bq  = (const float*)d_in[2];
    const float* Wk  = (const float*)d_in[3];
    const float* bk  = (const float*)d_in[4];
    const float* Wv  = (const float*)d_in[5];
    const float* bv  = (const float*)d_in[6];
    const float* Wo  = (const float*)d_in[7];
    const float* bo  = (const float*)d_in[8];
    const float* Wg  = (const float*)d_in[9];
    const float* bg  = (const float*)d_in[10];
    const float* gru = (const float*)d_in[11];
    const float* rel = (const float*)d_in[12];
    const float* l1g = (const float*)d_in[13];
    const float* l1b = (const float*)d_in[14];
    const float* W1  = (const float*)d_in[15];
    const float* b1  = (const float*)d_in[16];
    const float* W2  = (const float*)d_in[17];
    const float* b2  = (const float*)d_in[18];
    const float* l2g = (const float*)d_in[19];
    const float* l2b = (const float*)d_in[20];
    const float* Wad = (const float*)d_in[21];
    const float* bad = (const float*)d_in[22];
    const float* Wau = (const float*)d_in[23];
    const float* bau = (const float*)d_in[24];
    float* out = (float*)d_out;

    __half *pqkv, *pctx, *phr, *pff1, *pxr, *pwqkv, *pwo, *pw1c, *pw2c;
    float *patt, *ph, *pff2, *pgate, *ppb, *pbqkv, *pb2c, *pb1c, *pwgab;
    cudaGetSymbolAddress((void**)&pqkv, g_qkv);
    cudaGetSymbolAddress((void**)&pctx, g_ctx);
    cudaGetSymbolAddress((void**)&patt, g_att);
    cudaGetSymbolAddress((void**)&ph,   g_h);
    cudaGetSymbolAddress((void**)&phr,  g_hr);
    cudaGetSymbolAddress((void**)&pff1, g_ff1);
    cudaGetSymbolAddress((void**)&pff2, g_ff2);
    cudaGetSymbolAddress((void**)&pgate, g_gate);
    cudaGetSymbolAddress((void**)&ppb,  g_pb);
    cudaGetSymbolAddress((void**)&pxr,  g_xr);
    cudaGetSymbolAddress((void**)&pwqkv, g_wqkv);
    cudaGetSymbolAddress((void**)&pwo,  g_wo);
    cudaGetSymbolAddress((void**)&pw1c, g_w1c);
    cudaGetSymbolAddress((void**)&pw2c, g_w2c);
    cudaGetSymbolAddress((void**)&pbqkv, g_bqkv);
    cudaGetSymbolAddress((void**)&pb2c, g_b2c);
    cudaGetSymbolAddress((void**)&pb1c, g_b1c);
    cudaGetSymbolAddress((void**)&pwgab, g_wgab);

    cudaFuncSetAttribute(gemm_h<0,0>, cudaFuncAttributeMaxDynamicSharedMemorySize, HS_BYTES);
    cudaFuncSetAttribute(gemm_h<0,1>, cudaFuncAttributeMaxDynamicSharedMemorySize, HS_BYTES);
    cudaFuncSetAttribute(gemm_h<3,1>, cudaFuncAttributeMaxDynamicSharedMemorySize, HS_BYTES);
    cudaFuncSetAttribute(attn_tc, cudaFuncAttributeMaxDynamicSharedMemorySize, ATT_BYTES);

    // launches 1-3
    pack_weights<<<(PW_TOT + 255)/256, 256>>>(Wq, Wk, Wv, Wo, W1, Wad, W2, Wau,
                                              pwqkv, pwo, pw1c, pw2c);
    pack_h<<<(MM*HH)/2048, 256>>>(x, pxr, MM*HH);
    bias_prep<<<(4*HH + FAK + 130 + 255)/256, 256>>>(bq, bk, bv, b2, bau, b1, bad,
                                                     Wg, bg, pbqkv, pb2c, pb1c, pwgab);
    // 4) fused QKV projection
    gemm_h<0,1><<<dim3(QKVN/128, MM/128), 256, HS_BYTES>>>(pxr, pwqkv, pbqkv, pqkv, MM, QKVN, HH, QKVN);
    // 5-6) pos bias + gates
    pbias_kernel<<<(2047 + 127) / 128, 128>>>(rel, ppb);
    gate_kernel<<<MM/8, 256>>>(x, pwgab, gru, pgate);
    // 7) attention (register-resident P)
    attn_tc<<<dim3(SS/64, NHH, BB), 128, ATT_BYTES>>>(pqkv, pgate, ppb, pctx);
    // 8) output projection (float out)
    gemm_h<0,0><<<dim3(HH/128, MM/128), 256, HS_BYTES>>>(pctx, pwo, bo, patt, MM, HH, HH, HH);
    // 9) residual + LN1
    ln_kernel<<<MM, 256>>>(x, patt, l1g, l1b, ph, phr);
    // 10) fused FFN-up(gelu) + adapter-down(elu)
    gemm_h<3,1><<<dim3(FAK/128, MM/128), 256, HS_BYTES>>>(phr, pw1c, pb1c, pff1, MM, FAK, HH, FAK);
    // 11) fused FFN-down + adapter-up
    gemm_h<0,0><<<dim3(HH/128, MM/128), 256, HS_BYTES>>>(pff1, pw2c, pb2c, pff2, MM, HH, FAK, HH);
    // 12) h + (ff+adapt), LN2 -> out
    ln_kernel<<<MM, 256>>>(ph, pff2, l2g, l2b, out, nullptr);
}